// round 3
// baseline (speedup 1.0000x reference)
#include <cuda_runtime.h>
#include <cuda_bf16.h>
#include <math.h>

// Problem constants (fixed by setup_inputs)
#define NB    4        // batch
#define KDIR  4        // scan directions
#define NSEQ  16       // NB*KDIR
#define LL    4608     // sequence length
#define CC    256      // channels
#define DD    512      // d_in
#define MM    73728    // NSEQ*LL
#define HH    96
#define WW    96
#define HW    9216
#define RNK   16       // dt_rank
#define NST   16       // D_STATE

// ---------------- scratch (device globals; no allocation) ----------------
__device__ __align__(16) float g_xn [(size_t)MM * CC];    // layernormed gathered x
__device__ __align__(16) float g_xz [(size_t)MM * 1024];  // in_proj out: [xi | z]
__device__ __align__(16) float g_xc [(size_t)MM * DD];    // conv+silu
__device__ __align__(16) float g_dbc[(size_t)MM * 48];    // x_proj out: [dt_in | B | C]
__device__ __align__(16) float g_dt [(size_t)MM * DD];    // dt (softplus); reused as y after scan
__device__ __align__(16) float g_out[(size_t)MM * CC];    // out_proj result

// ---------------- K1: gather (JEGO scan) + LayerNorm ----------------
__global__ void k_gather_ln(const float* __restrict__ d0, const float* __restrict__ d1,
                            const float* __restrict__ nw, const float* __restrict__ nb)
{
    int l = blockIdx.x;          // 0..4607
    int n = blockIdx.y;          // 0..15
    int c = threadIdx.x;         // 0..255
    int b = n >> 2, k = n & 3;

    int src_l = (k < 2) ? l : (LL - 1 - l);
    int i = src_l / 96;
    int j = src_l % 96;
    int jj = (j < 48) ? j : (j - 48);
    const float* src = (j < 48) ? d0 : d1;

    int h, w;
    if      (k == 0) { h = 2*i;      w = 2*jj;     }
    else if (k == 1) { h = 2*jj + 1; w = 2*i + 1;  }
    else if (k == 2) { h = 2*i;      w = 2*jj + 1; }
    else             { h = 2*jj + 1; w = 2*i;      }

    float v = src[((size_t)(b*CC + c)*HH + h)*WW + w];

    // block reduce over 256 channels
    float s1 = v, s2 = v*v;
    #pragma unroll
    for (int o = 16; o > 0; o >>= 1) {
        s1 += __shfl_xor_sync(0xffffffffu, s1, o);
        s2 += __shfl_xor_sync(0xffffffffu, s2, o);
    }
    __shared__ float ssum[8], ssq[8];
    __shared__ float s_mean, s_rstd;
    int wid = c >> 5;
    if ((c & 31) == 0) { ssum[wid] = s1; ssq[wid] = s2; }
    __syncthreads();
    if (c == 0) {
        float t1 = 0.f, t2 = 0.f;
        #pragma unroll
        for (int q = 0; q < 8; q++) { t1 += ssum[q]; t2 += ssq[q]; }
        float mean = t1 * (1.f/256.f);
        float var  = t2 * (1.f/256.f) - mean*mean;
        s_mean = mean;
        s_rstd = rsqrtf(var + 1e-5f);
    }
    __syncthreads();

    g_xn[((size_t)n*LL + l)*CC + c] = (v - s_mean) * s_rstd * nw[c] + nb[c];
}

// ---------------- generic SGEMM: C[M,N] = A[M,K] * B[N,K]^T ----------------
template<int BM, int BN, int BK, int TM, int TN>
__global__ void sgemm_nt(const float* __restrict__ A, const float* __restrict__ B,
                         float* __restrict__ C, int Md, int Nd, int Kd)
{
    __shared__ float As[BK][BM + 4];
    __shared__ float Bs[BK][BN + 4];

    const int tid = threadIdx.x;             // 256 threads
    const int tx  = tid & 15;                // -> N
    const int ty  = tid >> 4;                // -> M
    const int m0  = blockIdx.y * BM;
    const int n0  = blockIdx.x * BN;

    float acc[TM][TN];
    #pragma unroll
    for (int a = 0; a < TM; a++)
        #pragma unroll
        for (int bq = 0; bq < TN; bq++) acc[a][bq] = 0.f;

    const int A4 = BM * BK / 4;
    const int B4 = BN * BK / 4;
    const int KV = BK / 4;

    for (int k0 = 0; k0 < Kd; k0 += BK) {
        for (int idx = tid; idx < A4; idx += 256) {
            int r = idx / KV, kk = (idx % KV) * 4;
            float4 v = *(const float4*)&A[(size_t)(m0 + r) * Kd + k0 + kk];
            As[kk+0][r] = v.x; As[kk+1][r] = v.y; As[kk+2][r] = v.z; As[kk+3][r] = v.w;
        }
        for (int idx = tid; idx < B4; idx += 256) {
            int r = idx / KV, kk = (idx % KV) * 4;
            float4 v = *(const float4*)&B[(size_t)(n0 + r) * Kd + k0 + kk];
            Bs[kk+0][r] = v.x; Bs[kk+1][r] = v.y; Bs[kk+2][r] = v.z; Bs[kk+3][r] = v.w;
        }
        __syncthreads();
        #pragma unroll
        for (int k = 0; k < BK; k++) {
            float av[TM], bv[TN];
            #pragma unroll
            for (int a = 0; a < TM; a++) av[a] = As[k][ty*TM + a];
            #pragma unroll
            for (int bq = 0; bq < TN; bq++) bv[bq] = Bs[k][tx*TN + bq];
            #pragma unroll
            for (int a = 0; a < TM; a++)
                #pragma unroll
                for (int bq = 0; bq < TN; bq++)
                    acc[a][bq] = fmaf(av[a], bv[bq], acc[a][bq]);
        }
        __syncthreads();
    }

    #pragma unroll
    for (int a = 0; a < TM; a++) {
        size_t rowo = (size_t)(m0 + ty*TM + a) * Nd + n0 + tx*TN;
        #pragma unroll
        for (int bq = 0; bq < TN; bq++)
            C[rowo + bq] = acc[a][bq];
    }
}

// ---------------- K3: causal depthwise conv (width 4) + SiLU ----------------
__global__ void k_conv_silu(const float* __restrict__ cw, const float* __restrict__ cb)
{
    int gid = blockIdx.x * 256 + threadIdx.x;   // over L*DD
    int n   = blockIdx.y;
    int e   = gid & (DD - 1);
    int l   = gid >> 9;
    size_t row = (size_t)n * LL + l;

    float acc = cb[e];
    #pragma unroll
    for (int t = 0; t < 4; t++) {
        int lt = l - 3 + t;
        if (lt >= 0)
            acc = fmaf(g_xz[((size_t)n*LL + lt)*1024 + e], cw[e*4 + t], acc);
    }
    float s = acc / (1.f + __expf(-acc));   // silu
    g_xc[row * DD + e] = s;
}

// ---------------- K5: dt = softplus(dbc[:, :16] @ dt_proj_w^T + b) ----------------
__global__ void k_dt(const float* __restrict__ dtw, const float* __restrict__ dtb)
{
    int gid = blockIdx.x * 256 + threadIdx.x;
    int n   = blockIdx.y;
    int e   = gid & (DD - 1);
    int l   = gid >> 9;
    size_t row = (size_t)n * LL + l;

    const float* dr = &g_dbc[row * 48];
    float v = dtb[e];
    #pragma unroll
    for (int r = 0; r < RNK; r++)
        v = fmaf(dr[r], dtw[e*RNK + r], v);

    float sp = (v > 20.f) ? v : log1pf(__expf(v));
    g_dt[row * DD + e] = sp;
}

// ---------------- K6: selective scan + D skip + z gating (y written in-place to g_dt) ----------------
__global__ void k_scan(const float* __restrict__ Alog, const float* __restrict__ Dp)
{
    int n = blockIdx.y;
    int e = blockIdx.x * 64 + threadIdx.x;

    float a[NST];
    #pragma unroll
    for (int s = 0; s < NST; s++) a[s] = -__expf(Alog[e*NST + s]);
    float a0 = a[0];

    bool fast = (a0 < 0.f);
    #pragma unroll
    for (int s = 0; s < NST; s++)
        fast = fast && (fabsf(a[s]/a0 - (float)(s+1)) < 1e-3f);

    float h[NST];
    #pragma unroll
    for (int s = 0; s < NST; s++) h[s] = 0.f;

    const float4* dbc4 = (const float4*)g_dbc;
    float De = Dp[e];

    if (fast) {
        for (int l = 0; l < LL; l++) {
            size_t row = (size_t)n*LL + l;
            float dtv = g_dt[row*DD + e];
            float xcv = g_xc[row*DD + e];
            float zv  = g_xz[row*1024 + DD + e];
            int b4 = (int)(row*12 + 4);
            float bb[NST], cc[NST];
            { float4 t = dbc4[b4+0]; bb[0]=t.x; bb[1]=t.y; bb[2]=t.z; bb[3]=t.w; }
            { float4 t = dbc4[b4+1]; bb[4]=t.x; bb[5]=t.y; bb[6]=t.z; bb[7]=t.w; }
            { float4 t = dbc4[b4+2]; bb[8]=t.x; bb[9]=t.y; bb[10]=t.z; bb[11]=t.w; }
            { float4 t = dbc4[b4+3]; bb[12]=t.x; bb[13]=t.y; bb[14]=t.z; bb[15]=t.w; }
            { float4 t = dbc4[b4+4]; cc[0]=t.x; cc[1]=t.y; cc[2]=t.z; cc[3]=t.w; }
            { float4 t = dbc4[b4+5]; cc[4]=t.x; cc[5]=t.y; cc[6]=t.z; cc[7]=t.w; }
            { float4 t = dbc4[b4+6]; cc[8]=t.x; cc[9]=t.y; cc[10]=t.z; cc[11]=t.w; }
            { float4 t = dbc4[b4+7]; cc[12]=t.x; cc[13]=t.y; cc[14]=t.z; cc[15]=t.w; }

            float w  = dtv * xcv;
            float p  = __expf(dtv * a0);     // dA_s = p^(s+1)
            float pk = p;
            float yv = 0.f;
            #pragma unroll
            for (int s = 0; s < NST; s++) {
                h[s] = fmaf(h[s], pk, w * bb[s]);
                yv   = fmaf(h[s], cc[s], yv);
                pk  *= p;
            }
            yv = (yv + xcv*De) * (zv / (1.f + __expf(-zv)));
            g_dt[row*DD + e] = yv;
        }
    } else {
        for (int l = 0; l < LL; l++) {
            size_t row = (size_t)n*LL + l;
            float dtv = g_dt[row*DD + e];
            float xcv = g_xc[row*DD + e];
            float zv  = g_xz[row*1024 + DD + e];
            int b4 = (int)(row*12 + 4);
            float bb[NST], cc[NST];
            { float4 t = dbc4[b4+0]; bb[0]=t.x; bb[1]=t.y; bb[2]=t.z; bb[3]=t.w; }
            { float4 t = dbc4[b4+1]; bb[4]=t.x; bb[5]=t.y; bb[6]=t.z; bb[7]=t.w; }
            { float4 t = dbc4[b4+2]; bb[8]=t.x; bb[9]=t.y; bb[10]=t.z; bb[11]=t.w; }
            { float4 t = dbc4[b4+3]; bb[12]=t.x; bb[13]=t.y; bb[14]=t.z; bb[15]=t.w; }
            { float4 t = dbc4[b4+4]; cc[0]=t.x; cc[1]=t.y; cc[2]=t.z; cc[3]=t.w; }
            { float4 t = dbc4[b4+5]; cc[4]=t.x; cc[5]=t.y; cc[6]=t.z; cc[7]=t.w; }
            { float4 t = dbc4[b4+6]; cc[8]=t.x; cc[9]=t.y; cc[10]=t.z; cc[11]=t.w; }
            { float4 t = dbc4[b4+7]; cc[12]=t.x; cc[13]=t.y; cc[14]=t.z; cc[15]=t.w; }

            float w  = dtv * xcv;
            float yv = 0.f;
            #pragma unroll
            for (int s = 0; s < NST; s++) {
                float dA = __expf(dtv * a[s]);
                h[s] = fmaf(h[s], dA, w * bb[s]);
                yv   = fmaf(h[s], cc[s], yv);
            }
            yv = (yv + xcv*De) * (zv / (1.f + __expf(-zv)));
            g_dt[row*DD + e] = yv;
        }
    }
}

// ---------------- K8: merge (inverse scatter) + residual: out = 2*desc + proj ----------------
__global__ void k_final(const float* __restrict__ d0, const float* __restrict__ d1,
                        float* __restrict__ out)
{
    int idx = blockIdx.x * 256 + threadIdx.x;   // over 2*4*256*96*96
    int w = idx % 96;
    int t = idx / 96;
    int h = t % 96; t /= 96;
    int c = t % 256; t /= 256;
    int b = t & 3;
    int d = t >> 2;

    int k, l;
    if ((h & 1) == 0) {
        if ((w & 1) == 0) { k = 0; l = (h>>1)*96 + (w>>1) + 48*d; }
        else              { k = 2; l = (LL-1) - ((h>>1)*96 + (w>>1) + 48*d); }
    } else {
        if ((w & 1) == 1) { k = 1; l = (w>>1)*96 + (h>>1) + 48*d; }
        else              { k = 3; l = (LL-1) - ((w>>1)*96 + (h>>1) + 48*d); }
    }
    int n = b*4 + k;
    const float* dsc = d ? d1 : d0;
    int local = idx - d * (NB*CC*HW);

    out[idx] = 2.f*dsc[local] + g_out[((size_t)n*LL + l)*CC + c];
}

// ---------------- host launch ----------------
extern "C" void kernel_launch(void* const* d_in, const int* in_sizes, int n_in,
                              void* d_out, int out_size)
{
    const float* desc0 = (const float*)d_in[0];
    const float* desc1 = (const float*)d_in[1];
    const float* nw    = (const float*)d_in[2];
    const float* nbi   = (const float*)d_in[3];
    const float* inw   = (const float*)d_in[4];   // (1024,256)
    const float* cw    = (const float*)d_in[5];   // (512,4)
    const float* cb    = (const float*)d_in[6];
    const float* xpw   = (const float*)d_in[7];   // (48,512)
    const float* dtw   = (const float*)d_in[8];   // (512,16)
    const float* dtb   = (const float*)d_in[9];
    const float* alog  = (const float*)d_in[10];  // (512,16)
    const float* dpar  = (const float*)d_in[11];
    const float* opw   = (const float*)d_in[12];  // (256,512)

    float *p_xn, *p_xz, *p_xc, *p_dbc, *p_dt, *p_out;
    cudaGetSymbolAddress((void**)&p_xn,  g_xn);
    cudaGetSymbolAddress((void**)&p_xz,  g_xz);
    cudaGetSymbolAddress((void**)&p_xc,  g_xc);
    cudaGetSymbolAddress((void**)&p_dbc, g_dbc);
    cudaGetSymbolAddress((void**)&p_dt,  g_dt);
    cudaGetSymbolAddress((void**)&p_out, g_out);

    // 1. gather + layernorm
    k_gather_ln<<<dim3(LL, NSEQ), 256>>>(desc0, desc1, nw, nbi);

    // 2. in_proj: (M,256) x (1024,256)^T -> (M,1024)
    sgemm_nt<128,64,16,8,4><<<dim3(1024/64, MM/128), 256>>>(p_xn, inw, p_xz, MM, 1024, 256);

    // 3. conv + silu
    k_conv_silu<<<dim3(LL*DD/256, NSEQ), 256>>>(cw, cb);

    // 4. x_proj: (M,512) x (48,512)^T -> (M,48)
    sgemm_nt<64,48,16,4,3><<<dim3(1, MM/64), 256>>>(p_xc, xpw, p_dbc, MM, 48, 512);

    // 5. dt projection + softplus
    k_dt<<<dim3(LL*DD/256, NSEQ), 256>>>(dtw, dtb);

    // 6. selective scan (+ D skip + z gate), y -> g_dt in place
    k_scan<<<dim3(DD/64, NSEQ), 64>>>(alog, dpar);

    // 7. out_proj: (M,512) x (256,512)^T -> (M,256)
    sgemm_nt<128,64,16,8,4><<<dim3(256/64, MM/128), 256>>>(p_dt, opw, p_out, MM, 256, 512);

    // 8. merge + residual
    k_final<<<dim3(out_size/256), 256>>>(desc0, desc1, (float*)d_out);
}

// round 5
// speedup vs baseline: 2.8371x; 2.8371x over previous
#include <cuda_runtime.h>
#include <cuda_bf16.h>
#include <cstdint>
#include <cstdio>
#include <math.h>

// Problem constants (fixed by setup_inputs)
#define NB    4
#define NSEQ  16
#define LL    4608
#define CC    256
#define DD    512
#define MM    73728
#define HH    96
#define WW    96
#define HW    9216
#define RNK   16
#define NST   16
#define NCHUNK 16
#define CH    288      // LL / NCHUNK

// ---------------- scratch (device globals; no allocation) ----------------
__device__ __align__(16) __nv_bfloat16 g_xnb[(size_t)MM * CC];    // LN'ed x (bf16, GEMM A)
__device__ __align__(16) float g_xz [(size_t)MM * 1024];          // in_proj out: [xi | z]
__device__ __align__(16) float g_xc [(size_t)MM * DD];            // conv+silu
__device__ __align__(16) float g_dbc[(size_t)MM * 48];            // x_proj out: [dt_in | B | C]
__device__ __align__(16) float g_dt [(size_t)MM * DD];            // dt (softplus)
__device__ __align__(16) __nv_bfloat16 g_ybf[(size_t)MM * DD];    // y (bf16, GEMM A)
__device__ __align__(16) float g_out[(size_t)MM * CC];            // out_proj result
__device__ __align__(16) __nv_bfloat16 g_wib[1024 * 256];         // in_proj_w bf16
__device__ __align__(16) __nv_bfloat16 g_wob[256 * 512];          // out_proj_w bf16
__device__ __align__(16) float g_P [(size_t)NSEQ * NCHUNK * DD * NST];  // chunk decay
__device__ __align__(16) float g_he[(size_t)NSEQ * NCHUNK * DD * NST];  // chunk local h_end
__device__ __align__(16) float g_h0[(size_t)NSEQ * NCHUNK * DD * NST];  // chunk initial h

// ---------------- K1: gather (JEGO scan) + LayerNorm -> bf16 ----------------
__global__ void k_gather_ln(const float* __restrict__ d0, const float* __restrict__ d1,
                            const float* __restrict__ nw, const float* __restrict__ nb)
{
    int l = blockIdx.x;
    int n = blockIdx.y;
    int c = threadIdx.x;
    int b = n >> 2, k = n & 3;

    int src_l = (k < 2) ? l : (LL - 1 - l);
    int i = src_l / 96;
    int j = src_l % 96;
    int jj = (j < 48) ? j : (j - 48);
    const float* src = (j < 48) ? d0 : d1;

    int h, w;
    if      (k == 0) { h = 2*i;      w = 2*jj;     }
    else if (k == 1) { h = 2*jj + 1; w = 2*i + 1;  }
    else if (k == 2) { h = 2*i;      w = 2*jj + 1; }
    else             { h = 2*jj + 1; w = 2*i;      }

    float v = src[((size_t)(b*CC + c)*HH + h)*WW + w];

    float s1 = v, s2 = v*v;
    #pragma unroll
    for (int o = 16; o > 0; o >>= 1) {
        s1 += __shfl_xor_sync(0xffffffffu, s1, o);
        s2 += __shfl_xor_sync(0xffffffffu, s2, o);
    }
    __shared__ float ssum[8], ssq[8];
    __shared__ float s_mean, s_rstd;
    int wid = c >> 5;
    if ((c & 31) == 0) { ssum[wid] = s1; ssq[wid] = s2; }
    __syncthreads();
    if (c == 0) {
        float t1 = 0.f, t2 = 0.f;
        #pragma unroll
        for (int q = 0; q < 8; q++) { t1 += ssum[q]; t2 += ssq[q]; }
        float mean = t1 * (1.f/256.f);
        float var  = t2 * (1.f/256.f) - mean*mean;
        s_mean = mean;
        s_rstd = rsqrtf(var + 1e-5f);
    }
    __syncthreads();

    float r = (v - s_mean) * s_rstd * nw[c] + nb[c];
    g_xnb[((size_t)n*LL + l)*CC + c] = __float2bfloat16(r);
}

// ---------------- weight conversion to bf16 ----------------
__global__ void k_cvtw(const float* __restrict__ inw, const float* __restrict__ opw)
{
    int i = blockIdx.x * 256 + threadIdx.x;
    if (i < 1024*256) g_wib[i] = __float2bfloat16(inw[i]);
    if (i < 256*512)  g_wob[i] = __float2bfloat16(opw[i]);
}

// ---------------- bf16 tensor-core GEMM: C[M,N] = A[M,K] * B[N,K]^T ----------------
__device__ __forceinline__ unsigned int smem_u32(const void* p) {
    return (unsigned int)__cvta_generic_to_shared(p);
}
__device__ __forceinline__ void ldsm4(unsigned int* r, unsigned int addr) {
    asm volatile("ldmatrix.sync.aligned.m8n8.x4.shared.b16 {%0,%1,%2,%3}, [%4];"
                 : "=r"(r[0]), "=r"(r[1]), "=r"(r[2]), "=r"(r[3]) : "r"(addr));
}
__device__ __forceinline__ void mma16816(float* c, const unsigned int* a,
                                         unsigned int b0, unsigned int b1) {
    asm volatile("mma.sync.aligned.m16n8k16.row.col.f32.bf16.bf16.f32 "
                 "{%0,%1,%2,%3},{%4,%5,%6,%7},{%8,%9},{%0,%1,%2,%3};"
                 : "+f"(c[0]), "+f"(c[1]), "+f"(c[2]), "+f"(c[3])
                 : "r"(a[0]), "r"(a[1]), "r"(a[2]), "r"(a[3]), "r"(b0), "r"(b1));
}

// BM=128, BN=64, BK=32, 256 threads (8 warps, 4x2), warp tile 32x32
__global__ void hgemm_nt(const __nv_bfloat16* __restrict__ A, const __nv_bfloat16* __restrict__ B,
                         float* __restrict__ C, int Md, int Nd, int Kd)
{
    const int LDS = 40;   // BK + 8 pad -> 80B row stride, conflict-free ldmatrix
    __shared__ __nv_bfloat16 As[128 * LDS];
    __shared__ __nv_bfloat16 Bs[64 * LDS];

    int tid  = threadIdx.x;
    int wid  = tid >> 5, lane = tid & 31;
    int wm   = (wid & 3) * 32;
    int wn   = (wid >> 2) * 32;
    int m0   = blockIdx.y * 128;
    int n0   = blockIdx.x * 64;

    float c[2][4][4];
    #pragma unroll
    for (int i = 0; i < 2; i++)
        #pragma unroll
        for (int j = 0; j < 4; j++)
            #pragma unroll
            for (int q = 0; q < 4; q++) c[i][j][q] = 0.f;

    int ar = tid >> 2;          // 0..63
    int ac = (tid & 3) * 8;     // 0,8,16,24

    for (int k0 = 0; k0 < Kd; k0 += 32) {
        *(uint4*)&As[ar * LDS + ac]        = *(const uint4*)&A[(size_t)(m0 + ar)      * Kd + k0 + ac];
        *(uint4*)&As[(ar + 64) * LDS + ac] = *(const uint4*)&A[(size_t)(m0 + ar + 64) * Kd + k0 + ac];
        *(uint4*)&Bs[ar * LDS + ac]        = *(const uint4*)&B[(size_t)(n0 + ar)      * Kd + k0 + ac];
        __syncthreads();

        #pragma unroll
        for (int ks = 0; ks < 2; ks++) {
            int kk = ks * 16;
            unsigned int a[2][4], b[2][4];
            #pragma unroll
            for (int i = 0; i < 2; i++) {
                unsigned int addr = smem_u32(&As[(wm + i*16 + (lane & 15)) * LDS + kk + ((lane >> 4) * 8)]);
                ldsm4(a[i], addr);
            }
            #pragma unroll
            for (int j = 0; j < 2; j++) {
                unsigned int addr = smem_u32(&Bs[(wn + j*16 + (lane & 15)) * LDS + kk + ((lane >> 4) * 8)]);
                ldsm4(b[j], addr);
            }
            #pragma unroll
            for (int i = 0; i < 2; i++)
                #pragma unroll
                for (int j = 0; j < 2; j++) {
                    mma16816(c[i][2*j+0], a[i], b[j][0], b[j][2]);
                    mma16816(c[i][2*j+1], a[i], b[j][1], b[j][3]);
                }
        }
        __syncthreads();
    }

    int g = lane >> 2, t4 = lane & 3;
    #pragma unroll
    for (int i = 0; i < 2; i++)
        #pragma unroll
        for (int j = 0; j < 4; j++) {
            int row = m0 + wm + i*16 + g;
            int col = n0 + wn + j*8 + t4*2;
            *(float2*)&C[(size_t)row * Nd + col]       = make_float2(c[i][j][0], c[i][j][1]);
            *(float2*)&C[(size_t)(row + 8) * Nd + col] = make_float2(c[i][j][2], c[i][j][3]);
        }
}

// ---------------- fp32 SGEMM (kept for x_proj, N=48) ----------------
template<int BM, int BN, int BK, int TM, int TN>
__global__ void sgemm_nt(const float* __restrict__ A, const float* __restrict__ B,
                         float* __restrict__ C, int Md, int Nd, int Kd)
{
    __shared__ float As[BK][BM + 4];
    __shared__ float Bs[BK][BN + 4];

    const int tid = threadIdx.x;
    const int tx  = tid & 15;
    const int ty  = tid >> 4;
    const int m0  = blockIdx.y * BM;
    const int n0  = blockIdx.x * BN;

    float acc[TM][TN];
    #pragma unroll
    for (int a = 0; a < TM; a++)
        #pragma unroll
        for (int bq = 0; bq < TN; bq++) acc[a][bq] = 0.f;

    const int A4 = BM * BK / 4;
    const int B4 = BN * BK / 4;
    const int KV = BK / 4;

    for (int k0 = 0; k0 < Kd; k0 += BK) {
        for (int idx = tid; idx < A4; idx += 256) {
            int r = idx / KV, kk = (idx % KV) * 4;
            float4 v = *(const float4*)&A[(size_t)(m0 + r) * Kd + k0 + kk];
            As[kk+0][r] = v.x; As[kk+1][r] = v.y; As[kk+2][r] = v.z; As[kk+3][r] = v.w;
        }
        for (int idx = tid; idx < B4; idx += 256) {
            int r = idx / KV, kk = (idx % KV) * 4;
            float4 v = *(const float4*)&B[(size_t)(n0 + r) * Kd + k0 + kk];
            Bs[kk+0][r] = v.x; Bs[kk+1][r] = v.y; Bs[kk+2][r] = v.z; Bs[kk+3][r] = v.w;
        }
        __syncthreads();
        #pragma unroll
        for (int k = 0; k < BK; k++) {
            float av[TM], bv[TN];
            #pragma unroll
            for (int a = 0; a < TM; a++) av[a] = As[k][ty*TM + a];
            #pragma unroll
            for (int bq = 0; bq < TN; bq++) bv[bq] = Bs[k][tx*TN + bq];
            #pragma unroll
            for (int a = 0; a < TM; a++)
                #pragma unroll
                for (int bq = 0; bq < TN; bq++)
                    acc[a][bq] = fmaf(av[a], bv[bq], acc[a][bq]);
        }
        __syncthreads();
    }

    #pragma unroll
    for (int a = 0; a < TM; a++) {
        size_t rowo = (size_t)(m0 + ty*TM + a) * Nd + n0 + tx*TN;
        #pragma unroll
        for (int bq = 0; bq < TN; bq++)
            C[rowo + bq] = acc[a][bq];
    }
}

// ---------------- causal depthwise conv (width 4) + SiLU ----------------
__global__ void k_conv_silu(const float* __restrict__ cw, const float* __restrict__ cb)
{
    int gid = blockIdx.x * 256 + threadIdx.x;
    int n   = blockIdx.y;
    int e   = gid & (DD - 1);
    int l   = gid >> 9;
    size_t row = (size_t)n * LL + l;

    float acc = cb[e];
    #pragma unroll
    for (int t = 0; t < 4; t++) {
        int lt = l - 3 + t;
        if (lt >= 0)
            acc = fmaf(g_xz[((size_t)n*LL + lt)*1024 + e], cw[e*4 + t], acc);
    }
    float s = acc / (1.f + __expf(-acc));
    g_xc[row * DD + e] = s;
}

// ---------------- dt = softplus(dbc[:, :16] @ dt_proj_w^T + b) ----------------
__global__ void k_dt(const float* __restrict__ dtw, const float* __restrict__ dtb)
{
    int gid = blockIdx.x * 256 + threadIdx.x;
    int n   = blockIdx.y;
    int e   = gid & (DD - 1);
    int l   = gid >> 9;
    size_t row = (size_t)n * LL + l;

    const float* dr = &g_dbc[row * 48];
    float v = dtb[e];
    #pragma unroll
    for (int r = 0; r < RNK; r++)
        v = fmaf(dr[r], dtw[e*RNK + r], v);

    float sp = (v > 20.f) ? v : log1pf(__expf(v));
    g_dt[row * DD + e] = sp;
}

// ---------------- scan pass 1: per-chunk local h_end + chunk decay P ----------------
__global__ void k_scan1(const float* __restrict__ Alog)
{
    int n  = blockIdx.z;
    int ch = blockIdx.y;
    int e  = blockIdx.x * 64 + threadIdx.x;

    float a[NST];
    #pragma unroll
    for (int s = 0; s < NST; s++) a[s] = -__expf(Alog[e*NST + s]);
    float a0 = a[0];

    bool fast = (a0 < 0.f);
    #pragma unroll
    for (int s = 0; s < NST; s++)
        fast = fast && (fabsf(a[s]/a0 - (float)(s+1)) < 1e-3f);

    float h[NST];
    #pragma unroll
    for (int s = 0; s < NST; s++) h[s] = 0.f;
    float sdt = 0.f;

    const float4* dbc4 = (const float4*)g_dbc;
    int l0 = ch * CH;

    if (fast) {
        for (int l = l0; l < l0 + CH; l++) {
            size_t row = (size_t)n*LL + l;
            float dtv = g_dt[row*DD + e];
            float xcv = g_xc[row*DD + e];
            size_t b4 = row*12 + 4;
            float bb[NST];
            { float4 t = dbc4[b4+0]; bb[0]=t.x; bb[1]=t.y; bb[2]=t.z; bb[3]=t.w; }
            { float4 t = dbc4[b4+1]; bb[4]=t.x; bb[5]=t.y; bb[6]=t.z; bb[7]=t.w; }
            { float4 t = dbc4[b4+2]; bb[8]=t.x; bb[9]=t.y; bb[10]=t.z; bb[11]=t.w; }
            { float4 t = dbc4[b4+3]; bb[12]=t.x; bb[13]=t.y; bb[14]=t.z; bb[15]=t.w; }
            float w = dtv * xcv;
            sdt += dtv;
            float p  = __expf(dtv * a0);
            float pk = p;
            #pragma unroll
            for (int s = 0; s < NST; s++) {
                h[s] = fmaf(h[s], pk, w * bb[s]);
                pk  *= p;
            }
        }
    } else {
        for (int l = l0; l < l0 + CH; l++) {
            size_t row = (size_t)n*LL + l;
            float dtv = g_dt[row*DD + e];
            float xcv = g_xc[row*DD + e];
            size_t b4 = row*12 + 4;
            float bb[NST];
            { float4 t = dbc4[b4+0]; bb[0]=t.x; bb[1]=t.y; bb[2]=t.z; bb[3]=t.w; }
            { float4 t = dbc4[b4+1]; bb[4]=t.x; bb[5]=t.y; bb[6]=t.z; bb[7]=t.w; }
            { float4 t = dbc4[b4+2]; bb[8]=t.x; bb[9]=t.y; bb[10]=t.z; bb[11]=t.w; }
            { float4 t = dbc4[b4+3]; bb[12]=t.x; bb[13]=t.y; bb[14]=t.z; bb[15]=t.w; }
            float w = dtv * xcv;
            sdt += dtv;
            #pragma unroll
            for (int s = 0; s < NST; s++) {
                float dA = __expf(dtv * a[s]);
                h[s] = fmaf(h[s], dA, w * bb[s]);
            }
        }
    }

    size_t o = (((size_t)n*NCHUNK + ch)*DD + e) * NST;
    #pragma unroll
    for (int q = 0; q < 4; q++) {
        ((float4*)&g_he[o])[q] = make_float4(h[4*q], h[4*q+1], h[4*q+2], h[4*q+3]);
        // P_s = prod_l exp(dt_l * a_s) = exp(a_s * sum dt_l)   (exact, both paths)
        ((float4*)&g_P[o])[q] = make_float4(__expf(a[4*q]*sdt),   __expf(a[4*q+1]*sdt),
                                            __expf(a[4*q+2]*sdt), __expf(a[4*q+3]*sdt));
    }
}

// ---------------- carry: sequential over 16 chunks ----------------
__global__ void k_carry()
{
    int idx = blockIdx.x * 256 + threadIdx.x;   // over NSEQ*DD = 8192
    int e = idx & (DD - 1);
    int n = idx >> 9;

    float hc[NST];
    #pragma unroll
    for (int s = 0; s < NST; s++) hc[s] = 0.f;

    for (int ch = 0; ch < NCHUNK; ch++) {
        size_t o = (((size_t)n*NCHUNK + ch)*DD + e) * NST;
        #pragma unroll
        for (int q = 0; q < 4; q++)
            ((float4*)&g_h0[o])[q] = make_float4(hc[4*q], hc[4*q+1], hc[4*q+2], hc[4*q+3]);
        #pragma unroll
        for (int q = 0; q < 4; q++) {
            float4 P = ((const float4*)&g_P[o])[q];
            float4 E = ((const float4*)&g_he[o])[q];
            hc[4*q+0] = fmaf(P.x, hc[4*q+0], E.x);
            hc[4*q+1] = fmaf(P.y, hc[4*q+1], E.y);
            hc[4*q+2] = fmaf(P.z, hc[4*q+2], E.z);
            hc[4*q+3] = fmaf(P.w, hc[4*q+3], E.w);
        }
    }
}

// ---------------- scan pass 2: full y with corrected h0, + D skip + z gate -> bf16 ----------------
__global__ void k_scan2(const float* __restrict__ Alog, const float* __restrict__ Dp)
{
    int n  = blockIdx.z;
    int ch = blockIdx.y;
    int e  = blockIdx.x * 64 + threadIdx.x;

    float a[NST];
    #pragma unroll
    for (int s = 0; s < NST; s++) a[s] = -__expf(Alog[e*NST + s]);
    float a0 = a[0];

    bool fast = (a0 < 0.f);
    #pragma unroll
    for (int s = 0; s < NST; s++)
        fast = fast && (fabsf(a[s]/a0 - (float)(s+1)) < 1e-3f);

    float h[NST];
    size_t o = (((size_t)n*NCHUNK + ch)*DD + e) * NST;
    #pragma unroll
    for (int q = 0; q < 4; q++) {
        float4 t = ((const float4*)&g_h0[o])[q];
        h[4*q] = t.x; h[4*q+1] = t.y; h[4*q+2] = t.z; h[4*q+3] = t.w;
    }

    const float4* dbc4 = (const float4*)g_dbc;
    float De = Dp[e];
    int l0 = ch * CH;

    if (fast) {
        for (int l = l0; l < l0 + CH; l++) {
            size_t row = (size_t)n*LL + l;
            float dtv = g_dt[row*DD + e];
            float xcv = g_xc[row*DD + e];
            float zv  = g_xz[row*1024 + DD + e];
            size_t b4 = row*12 + 4;
            float bb[NST], cc[NST];
            { float4 t = dbc4[b4+0]; bb[0]=t.x; bb[1]=t.y; bb[2]=t.z; bb[3]=t.w; }
            { float4 t = dbc4[b4+1]; bb[4]=t.x; bb[5]=t.y; bb[6]=t.z; bb[7]=t.w; }
            { float4 t = dbc4[b4+2]; bb[8]=t.x; bb[9]=t.y; bb[10]=t.z; bb[11]=t.w; }
            { float4 t = dbc4[b4+3]; bb[12]=t.x; bb[13]=t.y; bb[14]=t.z; bb[15]=t.w; }
            { float4 t = dbc4[b4+4]; cc[0]=t.x; cc[1]=t.y; cc[2]=t.z; cc[3]=t.w; }
            { float4 t = dbc4[b4+5]; cc[4]=t.x; cc[5]=t.y; cc[6]=t.z; cc[7]=t.w; }
            { float4 t = dbc4[b4+6]; cc[8]=t.x; cc[9]=t.y; cc[10]=t.z; cc[11]=t.w; }
            { float4 t = dbc4[b4+7]; cc[12]=t.x; cc[13]=t.y; cc[14]=t.z; cc[15]=t.w; }

            float w  = dtv * xcv;
            float p  = __expf(dtv * a0);
            float pk = p;
            float yv = 0.f;
            #pragma unroll
            for (int s = 0; s < NST; s++) {
                h[s] = fmaf(h[s], pk, w * bb[s]);
                yv   = fmaf(h[s], cc[s], yv);
                pk  *= p;
            }
            yv = (yv + xcv*De) * (zv / (1.f + __expf(-zv)));
            g_ybf[row*DD + e] = __float2bfloat16(yv);
        }
    } else {
        for (int l = l0; l < l0 + CH; l++) {
            size_t row = (size_t)n*LL + l;
            float dtv = g_dt[row*DD + e];
            float xcv = g_xc[row*DD + e];
            float zv  = g_xz[row*1024 + DD + e];
            size_t b4 = row*12 + 4;
            float bb[NST], cc[NST];
            { float4 t = dbc4[b4+0]; bb[0]=t.x; bb[1]=t.y; bb[2]=t.z; bb[3]=t.w; }
            { float4 t = dbc4[b4+1]; bb[4]=t.x; bb[5]=t.y; bb[6]=t.z; bb[7]=t.w; }
            { float4 t = dbc4[b4+2]; bb[8]=t.x; bb[9]=t.y; bb[10]=t.z; bb[11]=t.w; }
            { float4 t = dbc4[b4+3]; bb[12]=t.x; bb[13]=t.y; bb[14]=t.z; bb[15]=t.w; }
            { float4 t = dbc4[b4+4]; cc[0]=t.x; cc[1]=t.y; cc[2]=t.z; cc[3]=t.w; }
            { float4 t = dbc4[b4+5]; cc[4]=t.x; cc[5]=t.y; cc[6]=t.z; cc[7]=t.w; }
            { float4 t = dbc4[b4+6]; cc[8]=t.x; cc[9]=t.y; cc[10]=t.z; cc[11]=t.w; }
            { float4 t = dbc4[b4+7]; cc[12]=t.x; cc[13]=t.y; cc[14]=t.z; cc[15]=t.w; }

            float w  = dtv * xcv;
            float yv = 0.f;
            #pragma unroll
            for (int s = 0; s < NST; s++) {
                float dA = __expf(dtv * a[s]);
                h[s] = fmaf(h[s], dA, w * bb[s]);
                yv   = fmaf(h[s], cc[s], yv);
            }
            yv = (yv + xcv*De) * (zv / (1.f + __expf(-zv)));
            g_ybf[row*DD + e] = __float2bfloat16(yv);
        }
    }
}

// ---------------- merge (inverse scatter) + residual: out = 2*desc + proj ----------------
__global__ void k_final(const float* __restrict__ d0, const float* __restrict__ d1,
                        float* __restrict__ out)
{
    int idx = blockIdx.x * 256 + threadIdx.x;
    int w = idx % 96;
    int t = idx / 96;
    int h = t % 96; t /= 96;
    int c = t % 256; t /= 256;
    int b = t & 3;
    int d = t >> 2;

    int k, l;
    if ((h & 1) == 0) {
        if ((w & 1) == 0) { k = 0; l = (h>>1)*96 + (w>>1) + 48*d; }
        else              { k = 2; l = (LL-1) - ((h>>1)*96 + (w>>1) + 48*d); }
    } else {
        if ((w & 1) == 1) { k = 1; l = (w>>1)*96 + (h>>1) + 48*d; }
        else              { k = 3; l = (LL-1) - ((w>>1)*96 + (h>>1) + 48*d); }
    }
    int n = b*4 + k;
    const float* dsc = d ? d1 : d0;
    int local = idx - d * (NB*CC*HW);

    out[idx] = 2.f*dsc[local] + g_out[((size_t)n*LL + l)*CC + c];
}

// ---------------- host launch ----------------
extern "C" void kernel_launch(void* const* d_in, const int* in_sizes, int n_in,
                              void* d_out, int out_size)
{
    const float* desc0 = (const float*)d_in[0];
    const float* desc1 = (const float*)d_in[1];
    const float* nw    = (const float*)d_in[2];
    const float* nbi   = (const float*)d_in[3];
    const float* inw   = (const float*)d_in[4];   // (1024,256)
    const float* cw    = (const float*)d_in[5];   // (512,4)
    const float* cb    = (const float*)d_in[6];
    const float* xpw   = (const float*)d_in[7];   // (48,512)
    const float* dtw   = (const float*)d_in[8];   // (512,16)
    const float* dtb   = (const float*)d_in[9];
    const float* alog  = (const float*)d_in[10];  // (512,16)
    const float* dpar  = (const float*)d_in[11];
    const float* opw   = (const float*)d_in[12];  // (256,512)

    float *p_xz, *p_xc, *p_dbc, *p_out;
    __nv_bfloat16 *p_xnb, *p_ybf, *p_wib, *p_wob;
    cudaGetSymbolAddress((void**)&p_xnb, g_xnb);
    cudaGetSymbolAddress((void**)&p_xz,  g_xz);
    cudaGetSymbolAddress((void**)&p_xc,  g_xc);
    cudaGetSymbolAddress((void**)&p_dbc, g_dbc);
    cudaGetSymbolAddress((void**)&p_ybf, g_ybf);
    cudaGetSymbolAddress((void**)&p_out, g_out);
    cudaGetSymbolAddress((void**)&p_wib, g_wib);
    cudaGetSymbolAddress((void**)&p_wob, g_wob);

    // 1. gather + layernorm -> bf16
    k_gather_ln<<<dim3(LL, NSEQ), 256>>>(desc0, desc1, nw, nbi);

    // 1b. weights -> bf16
    k_cvtw<<<1024, 256>>>(inw, opw);

    // 2. in_proj (tensor cores): (M,256)x(1024,256)^T -> (M,1024) fp32
    hgemm_nt<<<dim3(1024/64, MM/128), 256>>>(p_xnb, p_wib, p_xz, MM, 1024, 256);

    // 3. conv + silu
    k_conv_silu<<<dim3(LL*DD/256, NSEQ), 256>>>(cw, cb);

    // 4. x_proj: (M,512)x(48,512)^T -> (M,48) fp32
    sgemm_nt<64,48,16,4,3><<<dim3(1, MM/64), 256>>>(p_xc, xpw, p_dbc, MM, 48, 512);

    // 5. dt projection + softplus
    k_dt<<<dim3(LL*DD/256, NSEQ), 256>>>(dtw, dtb);

    // 6. parallel chunked scan
    k_scan1<<<dim3(DD/64, NCHUNK, NSEQ), 64>>>(alog);
    k_carry<<<NSEQ*DD/256, 256>>>();
    k_scan2<<<dim3(DD/64, NCHUNK, NSEQ), 64>>>(alog, dpar);

    // 7. out_proj (tensor cores): (M,512)x(256,512)^T -> (M,256) fp32
    hgemm_nt<<<dim3(256/64, MM/128), 256>>>(p_ybf, p_wob, p_out, MM, 256, 512);

    // 8. merge + residual
    k_final<<<dim3(out_size/256), 256>>>(desc0, desc1, (float*)d_out);
}

// round 6
// speedup vs baseline: 4.4617x; 1.5726x over previous
#include <cuda_runtime.h>
#include <cuda_bf16.h>
#include <cstdint>
#include <math.h>

// Problem constants
#define NB    4
#define NSEQ  16
#define LL    4608
#define CC    256
#define DD    512
#define MM    73728
#define HH    96
#define WW    96
#define HW    9216
#define RNK   16
#define NST   16
#define NCHUNK 16
#define CH    288      // LL / NCHUNK

// ---------------- scratch (device globals) ----------------
__device__ __align__(16) __nv_bfloat16 g_xg [(size_t)MM * CC];   // gathered x (n,l,c) bf16
__device__ __align__(16) __nv_bfloat16 g_xnb[(size_t)MM * CC];   // LN'ed x bf16
__device__ __align__(16) __nv_bfloat16 g_xi [(size_t)MM * DD];   // in_proj xi half bf16
__device__ __align__(16) __nv_bfloat16 g_z  [(size_t)MM * DD];   // in_proj z half bf16
__device__ __align__(16) __nv_bfloat16 g_xcb[(size_t)MM * DD];   // conv+silu bf16
__device__ __align__(16) float g_dbc[(size_t)MM * 64];           // x_proj out (padded 64): [dt_in|B|C|pad]
__device__ __align__(16) __nv_bfloat16 g_ybf[(size_t)MM * DD];   // y bf16
__device__ __align__(16) float g_outT[(size_t)CC * MM];          // out_proj result, c-major
__device__ __align__(16) __nv_bfloat16 g_wib[1024 * 256];        // in_proj_w bf16
__device__ __align__(16) __nv_bfloat16 g_wob[256 * 512];         // out_proj_w bf16
__device__ __align__(16) __nv_bfloat16 g_wxb[64 * 512];          // x_proj_w bf16 padded 48->64
__device__ __align__(16) float g_P [(size_t)NSEQ * NCHUNK * DD * NST];
__device__ __align__(16) float g_he[(size_t)NSEQ * NCHUNK * DD * NST];
__device__ __align__(16) float g_h0[(size_t)NSEQ * NCHUNK * DD * NST];

// ---------------- K0: gather-transpose desc -> g_xg (n,l,c) bf16 ----------------
// grid: x=h(96), y=wt(3)*ct(8), z=b(4)*d(2); threads (32,8)
__global__ void k_trans(const float* __restrict__ d0, const float* __restrict__ d1)
{
    __shared__ float tile[32][33];
    int h  = blockIdx.x;
    int wt = blockIdx.y % 3, ct = blockIdx.y / 3;
    int bd = blockIdx.z;
    int b = bd >> 1, d = bd & 1;
    int w0 = wt * 32, c0 = ct * 32;
    int tx = threadIdx.x, ty = threadIdx.y;

    const float* src = d ? d1 : d0;
    #pragma unroll
    for (int s = 0; s < 4; s++) {
        int cl = ty + s * 8;
        tile[cl][tx] = src[((size_t)(b*CC + c0 + cl)*HH + h)*WW + w0 + tx];
    }
    __syncthreads();

    #pragma unroll
    for (int s = 0; s < 4; s++) {
        int wl = ty + s * 8;
        int w  = w0 + wl;
        float v = tile[tx][wl];
        int k, l;
        if ((h & 1) == 0) {
            if ((w & 1) == 0) { k = 0; l = (h>>1)*96 + (w>>1) + 48*d; }
            else              { k = 2; l = (LL-1) - ((h>>1)*96 + (w>>1) + 48*d); }
        } else {
            if ((w & 1) == 1) { k = 1; l = (w>>1)*96 + (h>>1) + 48*d; }
            else              { k = 3; l = (LL-1) - ((w>>1)*96 + (h>>1) + 48*d); }
        }
        int n = b*4 + k;
        g_xg[((size_t)n*LL + l)*CC + c0 + tx] = __float2bfloat16(v);
    }
}

// ---------------- K1: LayerNorm over c (coalesced) -> bf16 ----------------
__global__ void k_ln(const float* __restrict__ nw, const float* __restrict__ nb)
{
    int l = blockIdx.x, n = blockIdx.y, c = threadIdx.x;
    size_t row = (size_t)n*LL + l;
    float v = __bfloat162float(g_xg[row*CC + c]);

    float s1 = v, s2 = v*v;
    #pragma unroll
    for (int o = 16; o > 0; o >>= 1) {
        s1 += __shfl_xor_sync(0xffffffffu, s1, o);
        s2 += __shfl_xor_sync(0xffffffffu, s2, o);
    }
    __shared__ float ssum[8], ssq[8];
    __shared__ float s_mean, s_rstd;
    int wid = c >> 5;
    if ((c & 31) == 0) { ssum[wid] = s1; ssq[wid] = s2; }
    __syncthreads();
    if (c == 0) {
        float t1 = 0.f, t2 = 0.f;
        #pragma unroll
        for (int q = 0; q < 8; q++) { t1 += ssum[q]; t2 += ssq[q]; }
        float mean = t1 * (1.f/256.f);
        float var  = t2 * (1.f/256.f) - mean*mean;
        s_mean = mean;
        s_rstd = rsqrtf(var + 1e-5f);
    }
    __syncthreads();

    g_xnb[row*CC + c] = __float2bfloat16((v - s_mean) * s_rstd * nw[c] + nb[c]);
}

// ---------------- weight conversion ----------------
__global__ void k_cvtw(const float* __restrict__ inw, const float* __restrict__ opw,
                       const float* __restrict__ xpw)
{
    int i = blockIdx.x * 256 + threadIdx.x;   // 0..262143
    if (i < 1024*256) g_wib[i] = __float2bfloat16(inw[i]);
    if (i < 256*512)  g_wob[i] = __float2bfloat16(opw[i]);
    if (i < 64*512) {
        int r = i >> 9, cidx = i & 511;
        g_wxb[i] = __float2bfloat16(r < 48 ? xpw[r*512 + cidx] : 0.f);
    }
}

// ---------------- mma helpers ----------------
__device__ __forceinline__ unsigned int smem_u32(const void* p) {
    return (unsigned int)__cvta_generic_to_shared(p);
}
__device__ __forceinline__ void ldsm4(unsigned int* r, unsigned int addr) {
    asm volatile("ldmatrix.sync.aligned.m8n8.x4.shared.b16 {%0,%1,%2,%3}, [%4];"
                 : "=r"(r[0]), "=r"(r[1]), "=r"(r[2]), "=r"(r[3]) : "r"(addr));
}
__device__ __forceinline__ void mma16816(float* c, const unsigned int* a,
                                         unsigned int b0, unsigned int b1) {
    asm volatile("mma.sync.aligned.m16n8k16.row.col.f32.bf16.bf16.f32 "
                 "{%0,%1,%2,%3},{%4,%5,%6,%7},{%8,%9},{%0,%1,%2,%3};"
                 : "+f"(c[0]), "+f"(c[1]), "+f"(c[2]), "+f"(c[3])
                 : "r"(a[0]), "r"(a[1]), "r"(a[2]), "r"(a[3]), "r"(b0), "r"(b1));
}

// ---------------- hgemm 128x128x32: C = A[M,K] * B[N,K]^T ----------------
// MODE 1: split bf16 output (cols<512 -> O1, else O2), Nd=1024
// MODE 2: fp32 transposed output C[col*MM + row]
template<int MODE>
__global__ __launch_bounds__(256) void hgemm128(
    const __nv_bfloat16* __restrict__ A, const __nv_bfloat16* __restrict__ B,
    float* __restrict__ C, __nv_bfloat16* __restrict__ O1, __nv_bfloat16* __restrict__ O2,
    int Md, int Nd, int Kd)
{
    const int LDS = 40;
    __shared__ __nv_bfloat16 As[128 * LDS];
    __shared__ __nv_bfloat16 Bs[128 * LDS];

    int tid  = threadIdx.x;
    int wid  = tid >> 5, lane = tid & 31;
    int wm   = (wid & 1) * 64;     // 2 warps in M, 4 m-frags each
    int wn   = (wid >> 1) * 32;    // 4 warps in N, 4 n-frags each
    int m0   = blockIdx.y * 128;
    int n0   = blockIdx.x * 128;

    float c[4][4][4];
    #pragma unroll
    for (int i = 0; i < 4; i++)
        #pragma unroll
        for (int j = 0; j < 4; j++)
            #pragma unroll
            for (int q = 0; q < 4; q++) c[i][j][q] = 0.f;

    int ar = tid >> 2;          // 0..63
    int ac = (tid & 3) * 8;

    for (int k0 = 0; k0 < Kd; k0 += 32) {
        *(uint4*)&As[ar * LDS + ac]        = *(const uint4*)&A[(size_t)(m0 + ar)      * Kd + k0 + ac];
        *(uint4*)&As[(ar + 64) * LDS + ac] = *(const uint4*)&A[(size_t)(m0 + ar + 64) * Kd + k0 + ac];
        *(uint4*)&Bs[ar * LDS + ac]        = *(const uint4*)&B[(size_t)(n0 + ar)      * Kd + k0 + ac];
        *(uint4*)&Bs[(ar + 64) * LDS + ac] = *(const uint4*)&B[(size_t)(n0 + ar + 64) * Kd + k0 + ac];
        __syncthreads();

        #pragma unroll
        for (int ks = 0; ks < 2; ks++) {
            int kk = ks * 16;
            unsigned int a[4][4], b[2][4];
            #pragma unroll
            for (int i = 0; i < 4; i++)
                ldsm4(a[i], smem_u32(&As[(wm + i*16 + (lane & 15)) * LDS + kk + ((lane >> 4) * 8)]));
            #pragma unroll
            for (int j2 = 0; j2 < 2; j2++)
                ldsm4(b[j2], smem_u32(&Bs[(wn + j2*16 + (lane & 15)) * LDS + kk + ((lane >> 4) * 8)]));
            #pragma unroll
            for (int i = 0; i < 4; i++)
                #pragma unroll
                for (int j2 = 0; j2 < 2; j2++) {
                    mma16816(c[i][2*j2+0], a[i], b[j2][0], b[j2][2]);
                    mma16816(c[i][2*j2+1], a[i], b[j2][1], b[j2][3]);
                }
        }
        __syncthreads();
    }

    int g = lane >> 2, t4 = lane & 3;
    #pragma unroll
    for (int i = 0; i < 4; i++)
        #pragma unroll
        for (int j = 0; j < 4; j++) {
            int row = m0 + wm + i*16 + g;
            int col = n0 + wn + j*8 + t4*2;
            if (MODE == 1) {
                __nv_bfloat162 v01 = __floats2bfloat162_rn(c[i][j][0], c[i][j][1]);
                __nv_bfloat162 v23 = __floats2bfloat162_rn(c[i][j][2], c[i][j][3]);
                if (col < 512) {
                    *(__nv_bfloat162*)&O1[(size_t)row * 512 + col]       = v01;
                    *(__nv_bfloat162*)&O1[(size_t)(row + 8) * 512 + col] = v23;
                } else {
                    *(__nv_bfloat162*)&O2[(size_t)row * 512 + col - 512]       = v01;
                    *(__nv_bfloat162*)&O2[(size_t)(row + 8) * 512 + col - 512] = v23;
                }
            } else {
                C[(size_t)col * MM + row]           = c[i][j][0];
                C[(size_t)(col+1) * MM + row]       = c[i][j][1];
                C[(size_t)col * MM + row + 8]       = c[i][j][2];
                C[(size_t)(col+1) * MM + row + 8]   = c[i][j][3];
            }
        }
}

// ---------------- x_proj GEMM with fused conv+silu A-build ----------------
// C[M,64] = conv_silu(xi)[M,512] * wxb[64,512]^T ; also writes xc bf16.
// BM=128, BN=64, BK=32, 256 threads, warps 4(M)x2(N), warp tile 32x32
__global__ __launch_bounds__(256) void k_xproj(const float* __restrict__ cw, const float* __restrict__ cb)
{
    const int LDS = 40;
    __shared__ __nv_bfloat16 As[128 * LDS];
    __shared__ __nv_bfloat16 Bs[64 * LDS];
    __shared__ float scw[512*4];
    __shared__ float scb[512];

    int tid = threadIdx.x;
    int wid = tid >> 5, lane = tid & 31;
    int wm  = (wid & 3) * 32;
    int wn  = (wid >> 2) * 32;
    int m0  = blockIdx.x * 128;

    for (int i = tid; i < 2048; i += 256) scw[i] = cw[i];
    for (int i = tid; i < 512;  i += 256) scb[i] = cb[i];

    float c[2][4][4];
    #pragma unroll
    for (int i = 0; i < 2; i++)
        #pragma unroll
        for (int j = 0; j < 4; j++)
            #pragma unroll
            for (int q = 0; q < 4; q++) c[i][j][q] = 0.f;

    int R  = tid >> 2;          // 0..63 (rows R and R+64)
    int k8 = (tid & 3) * 8;
    // sequence-local positions (tiles are 128-aligned; LL=4608=36*128 so rows stay in-seq)
    int lr1 = (m0 + R) % LL;
    int lr2 = (m0 + R + 64) % LL;
    __syncthreads();

    for (int k0 = 0; k0 < 512; k0 += 32) {
        #pragma unroll
        for (int pass = 0; pass < 2; pass++) {
            int r  = R + pass*64;
            int m  = m0 + r;
            int lr = pass ? lr2 : lr1;
            float acc[8];
            #pragma unroll
            for (int q = 0; q < 8; q++) acc[q] = scb[k0 + k8 + q];
            #pragma unroll
            for (int t = 0; t < 4; t++) {
                if (lr - 3 + t >= 0) {
                    uint4 u = *(const uint4*)&g_xi[(size_t)(m - 3 + t)*512 + k0 + k8];
                    __nv_bfloat162* p = (__nv_bfloat162*)&u;
                    #pragma unroll
                    for (int q2 = 0; q2 < 4; q2++) {
                        float2 f = __bfloat1622float2(p[q2]);
                        acc[2*q2+0] = fmaf(f.x, scw[(k0+k8+2*q2+0)*4 + t], acc[2*q2+0]);
                        acc[2*q2+1] = fmaf(f.y, scw[(k0+k8+2*q2+1)*4 + t], acc[2*q2+1]);
                    }
                }
            }
            uint4 o;
            __nv_bfloat162* q = (__nv_bfloat162*)&o;
            #pragma unroll
            for (int q2 = 0; q2 < 4; q2++) {
                float v0 = acc[2*q2+0], v1 = acc[2*q2+1];
                v0 = v0 / (1.f + __expf(-v0));
                v1 = v1 / (1.f + __expf(-v1));
                q[q2] = __floats2bfloat162_rn(v0, v1);
            }
            *(uint4*)&As[r * LDS + k8] = o;
            *(uint4*)&g_xcb[(size_t)m * 512 + k0 + k8] = o;   // materialize xc
        }
        // B: 64 rows x 32
        *(uint4*)&Bs[R * LDS + k8] = *(const uint4*)&g_wxb[(size_t)R * 512 + k0 + k8];
        __syncthreads();

        #pragma unroll
        for (int ks = 0; ks < 2; ks++) {
            int kk = ks * 16;
            unsigned int a[2][4], b[2][4];
            #pragma unroll
            for (int i = 0; i < 2; i++)
                ldsm4(a[i], smem_u32(&As[(wm + i*16 + (lane & 15)) * LDS + kk + ((lane >> 4) * 8)]));
            #pragma unroll
            for (int j2 = 0; j2 < 2; j2++)
                ldsm4(b[j2], smem_u32(&Bs[(wn + j2*16 + (lane & 15)) * LDS + kk + ((lane >> 4) * 8)]));
            #pragma unroll
            for (int i = 0; i < 2; i++)
                #pragma unroll
                for (int j2 = 0; j2 < 2; j2++) {
                    mma16816(c[i][2*j2+0], a[i], b[j2][0], b[j2][2]);
                    mma16816(c[i][2*j2+1], a[i], b[j2][1], b[j2][3]);
                }
        }
        __syncthreads();
    }

    int g = lane >> 2, t4 = lane & 3;
    #pragma unroll
    for (int i = 0; i < 2; i++)
        #pragma unroll
        for (int j = 0; j < 4; j++) {
            int row = m0 + wm + i*16 + g;
            int col = wn + j*8 + t4*2;
            *(float2*)&g_dbc[(size_t)row * 64 + col]       = make_float2(c[i][j][0], c[i][j][1]);
            *(float2*)&g_dbc[(size_t)(row + 8) * 64 + col] = make_float2(c[i][j][2], c[i][j][3]);
        }
}

// ---------------- scan helpers: inline dt from dbc ----------------
__device__ __forceinline__ float inline_dt(const float* __restrict__ dr, const float* dtwr, float dtbv)
{
    float v = dtbv;
    #pragma unroll
    for (int r = 0; r < RNK; r++) v = fmaf(dr[r], dtwr[r], v);
    return (v > 20.f) ? v : log1pf(__expf(v));
}

// ---------------- scan pass 1: per-chunk local h_end + chunk decay P ----------------
__global__ void k_scan1(const float* __restrict__ Alog,
                        const float* __restrict__ dtw, const float* __restrict__ dtb)
{
    int n  = blockIdx.z;
    int ch = blockIdx.y;
    int e  = blockIdx.x * 128 + threadIdx.x;

    float a[NST];
    #pragma unroll
    for (int s = 0; s < NST; s++) a[s] = -__expf(Alog[e*NST + s]);
    float a0 = a[0];
    bool fast = (a0 < 0.f);
    #pragma unroll
    for (int s = 0; s < NST; s++)
        fast = fast && (fabsf(a[s]/a0 - (float)(s+1)) < 1e-3f);

    float dtwr[RNK];
    #pragma unroll
    for (int r = 0; r < RNK; r++) dtwr[r] = dtw[e*RNK + r];
    float dtbv = dtb[e];

    float h[NST];
    #pragma unroll
    for (int s = 0; s < NST; s++) h[s] = 0.f;
    float sdt = 0.f;
    int l0 = ch * CH;

    for (int l = l0; l < l0 + CH; l++) {
        size_t row = (size_t)n*LL + l;
        const float* dr = &g_dbc[row * 64];
        float dv[RNK], bb[NST];
        #pragma unroll
        for (int q = 0; q < 4; q++) {
            float4 t0 = ((const float4*)dr)[q];
            dv[4*q]=t0.x; dv[4*q+1]=t0.y; dv[4*q+2]=t0.z; dv[4*q+3]=t0.w;
            float4 t1 = ((const float4*)dr)[4+q];
            bb[4*q]=t1.x; bb[4*q+1]=t1.y; bb[4*q+2]=t1.z; bb[4*q+3]=t1.w;
        }
        float dtv = inline_dt(dv, dtwr, dtbv);
        float xcv = __bfloat162float(g_xcb[row*DD + e]);
        float w = dtv * xcv;
        sdt += dtv;
        if (fast) {
            float p  = __expf(dtv * a0);
            float pk = p;
            #pragma unroll
            for (int s = 0; s < NST; s++) { h[s] = fmaf(h[s], pk, w * bb[s]); pk *= p; }
        } else {
            #pragma unroll
            for (int s = 0; s < NST; s++) {
                float dA = __expf(dtv * a[s]);
                h[s] = fmaf(h[s], dA, w * bb[s]);
            }
        }
    }

    size_t o = (((size_t)n*NCHUNK + ch)*DD + e) * NST;
    #pragma unroll
    for (int q = 0; q < 4; q++) {
        ((float4*)&g_he[o])[q] = make_float4(h[4*q], h[4*q+1], h[4*q+2], h[4*q+3]);
        ((float4*)&g_P[o])[q] = make_float4(__expf(a[4*q]*sdt),   __expf(a[4*q+1]*sdt),
                                            __expf(a[4*q+2]*sdt), __expf(a[4*q+3]*sdt));
    }
}

// ---------------- carry ----------------
__global__ void k_carry()
{
    int idx = blockIdx.x * 256 + threadIdx.x;
    int e = idx & (DD - 1);
    int n = idx >> 9;

    float hc[NST];
    #pragma unroll
    for (int s = 0; s < NST; s++) hc[s] = 0.f;

    for (int ch = 0; ch < NCHUNK; ch++) {
        size_t o = (((size_t)n*NCHUNK + ch)*DD + e) * NST;
        #pragma unroll
        for (int q = 0; q < 4; q++)
            ((float4*)&g_h0[o])[q] = make_float4(hc[4*q], hc[4*q+1], hc[4*q+2], hc[4*q+3]);
        #pragma unroll
        for (int q = 0; q < 4; q++) {
            float4 P = ((const float4*)&g_P[o])[q];
            float4 E = ((const float4*)&g_he[o])[q];
            hc[4*q+0] = fmaf(P.x, hc[4*q+0], E.x);
            hc[4*q+1] = fmaf(P.y, hc[4*q+1], E.y);
            hc[4*q+2] = fmaf(P.z, hc[4*q+2], E.z);
            hc[4*q+3] = fmaf(P.w, hc[4*q+3], E.w);
        }
    }
}

// ---------------- scan pass 2: y + D skip + z gate -> bf16 ----------------
__global__ void k_scan2(const float* __restrict__ Alog, const float* __restrict__ Dp,
                        const float* __restrict__ dtw, const float* __restrict__ dtb)
{
    int n  = blockIdx.z;
    int ch = blockIdx.y;
    int e  = blockIdx.x * 128 + threadIdx.x;

    float a[NST];
    #pragma unroll
    for (int s = 0; s < NST; s++) a[s] = -__expf(Alog[e*NST + s]);
    float a0 = a[0];
    bool fast = (a0 < 0.f);
    #pragma unroll
    for (int s = 0; s < NST; s++)
        fast = fast && (fabsf(a[s]/a0 - (float)(s+1)) < 1e-3f);

    float dtwr[RNK];
    #pragma unroll
    for (int r = 0; r < RNK; r++) dtwr[r] = dtw[e*RNK + r];
    float dtbv = dtb[e];
    float De = Dp[e];

    float h[NST];
    size_t o = (((size_t)n*NCHUNK + ch)*DD + e) * NST;
    #pragma unroll
    for (int q = 0; q < 4; q++) {
        float4 t = ((const float4*)&g_h0[o])[q];
        h[4*q] = t.x; h[4*q+1] = t.y; h[4*q+2] = t.z; h[4*q+3] = t.w;
    }

    int l0 = ch * CH;
    for (int l = l0; l < l0 + CH; l++) {
        size_t row = (size_t)n*LL + l;
        const float* dr = &g_dbc[row * 64];
        float dv[RNK], bb[NST], cc[NST];
        #pragma unroll
        for (int q = 0; q < 4; q++) {
            float4 t0 = ((const float4*)dr)[q];
            dv[4*q]=t0.x; dv[4*q+1]=t0.y; dv[4*q+2]=t0.z; dv[4*q+3]=t0.w;
            float4 t1 = ((const float4*)dr)[4+q];
            bb[4*q]=t1.x; bb[4*q+1]=t1.y; bb[4*q+2]=t1.z; bb[4*q+3]=t1.w;
            float4 t2 = ((const float4*)dr)[8+q];
            cc[4*q]=t2.x; cc[4*q+1]=t2.y; cc[4*q+2]=t2.z; cc[4*q+3]=t2.w;
        }
        float dtv = inline_dt(dv, dtwr, dtbv);
        float xcv = __bfloat162float(g_xcb[row*DD + e]);
        float zv  = __bfloat162float(g_z[row*DD + e]);
        float w  = dtv * xcv;
        float yv = 0.f;
        if (fast) {
            float p  = __expf(dtv * a0);
            float pk = p;
            #pragma unroll
            for (int s = 0; s < NST; s++) {
                h[s] = fmaf(h[s], pk, w * bb[s]);
                yv   = fmaf(h[s], cc[s], yv);
                pk  *= p;
            }
        } else {
            #pragma unroll
            for (int s = 0; s < NST; s++) {
                float dA = __expf(dtv * a[s]);
                h[s] = fmaf(h[s], dA, w * bb[s]);
                yv   = fmaf(h[s], cc[s], yv);
            }
        }
        yv = (yv + xcv*De) * (zv / (1.f + __expf(-zv)));
        g_ybf[row*DD + e] = __float2bfloat16(yv);
    }
}

// ---------------- merge + residual: out = 2*desc + projT ----------------
__global__ void k_final(const float* __restrict__ d0, const float* __restrict__ d1,
                        float* __restrict__ out)
{
    int idx = blockIdx.x * 256 + threadIdx.x;
    int w = idx % 96;
    int t = idx / 96;
    int h = t % 96; t /= 96;
    int c = t % 256; t /= 256;
    int b = t & 3;
    int d = t >> 2;

    int k, l;
    if ((h & 1) == 0) {
        if ((w & 1) == 0) { k = 0; l = (h>>1)*96 + (w>>1) + 48*d; }
        else              { k = 2; l = (LL-1) - ((h>>1)*96 + (w>>1) + 48*d); }
    } else {
        if ((w & 1) == 1) { k = 1; l = (w>>1)*96 + (h>>1) + 48*d; }
        else              { k = 3; l = (LL-1) - ((w>>1)*96 + (h>>1) + 48*d); }
    }
    int n = b*4 + k;
    const float* dsc = d ? d1 : d0;
    int local = idx - d * (NB*CC*HW);

    out[idx] = 2.f*dsc[local] + g_outT[(size_t)c * MM + (size_t)n*LL + l];
}

// ---------------- host launch ----------------
extern "C" void kernel_launch(void* const* d_in, const int* in_sizes, int n_in,
                              void* d_out, int out_size)
{
    const float* desc0 = (const float*)d_in[0];
    const float* desc1 = (const float*)d_in[1];
    const float* nw    = (const float*)d_in[2];
    const float* nbi   = (const float*)d_in[3];
    const float* inw   = (const float*)d_in[4];
    const float* cw    = (const float*)d_in[5];
    const float* cb    = (const float*)d_in[6];
    const float* xpw   = (const float*)d_in[7];
    const float* dtw   = (const float*)d_in[8];
    const float* dtb   = (const float*)d_in[9];
    const float* alog  = (const float*)d_in[10];
    const float* dpar  = (const float*)d_in[11];
    const float* opw   = (const float*)d_in[12];

    float *p_outT;
    __nv_bfloat16 *p_xnb, *p_ybf, *p_wib, *p_wob, *p_xi, *p_z;
    cudaGetSymbolAddress((void**)&p_xnb, g_xnb);
    cudaGetSymbolAddress((void**)&p_xi,  g_xi);
    cudaGetSymbolAddress((void**)&p_z,   g_z);
    cudaGetSymbolAddress((void**)&p_ybf, g_ybf);
    cudaGetSymbolAddress((void**)&p_outT, g_outT);
    cudaGetSymbolAddress((void**)&p_wib, g_wib);
    cudaGetSymbolAddress((void**)&p_wob, g_wob);

    // 0. gather-transpose
    k_trans<<<dim3(96, 24, 8), dim3(32, 8)>>>(desc0, desc1);
    // 0b. weights -> bf16
    k_cvtw<<<1024, 256>>>(inw, opw, xpw);
    // 1. layernorm
    k_ln<<<dim3(LL, NSEQ), 256>>>(nw, nbi);
    // 2. in_proj: (M,256)x(1024,256)^T -> xi,z bf16
    hgemm128<1><<<dim3(1024/128, MM/128), 256>>>(p_xnb, p_wib, nullptr, p_xi, p_z, MM, 1024, 256);
    // 3+4. conv+silu fused into x_proj GEMM (writes xc bf16 + dbc fp32)
    k_xproj<<<dim3(MM/128), 256>>>(cw, cb);
    // 5. parallel chunked scan (dt inline)
    k_scan1<<<dim3(DD/128, NCHUNK, NSEQ), 128>>>(alog, dtw, dtb);
    k_carry<<<NSEQ*DD/256, 256>>>();
    k_scan2<<<dim3(DD/128, NCHUNK, NSEQ), 128>>>(alog, dpar, dtw, dtb);
    // 6. out_proj: (M,512)x(256,512)^T -> fp32 transposed
    hgemm128<2><<<dim3(256/128, MM/128), 256>>>(p_ybf, p_wob, p_outT, nullptr, nullptr, MM, 256, 512);
    // 7. merge + residual
    k_final<<<dim3(out_size/256), 256>>>(desc0, desc1, (float*)d_out);
}

// round 7
// speedup vs baseline: 4.6023x; 1.0315x over previous
#include <cuda_runtime.h>
#include <cuda_bf16.h>
#include <cstdint>
#include <math.h>

// Problem constants
#define NB    4
#define NSEQ  16
#define LL    4608
#define CC    256
#define DD    512
#define MM    73728
#define HH    96
#define WW    96
#define HW    9216
#define RNK   16
#define NST   16
#define NCHUNK 16
#define CH    288      // LL / NCHUNK
#define SUB   72       // dbc smem slab rows (CH/SUB = 4)

// ---------------- scratch (device globals) ----------------
__device__ __align__(16) __nv_bfloat16 g_xg [(size_t)MM * CC];   // gathered x (n,l,c) bf16
__device__ __align__(16) float g_mu[MM];                         // LN mean per row
__device__ __align__(16) float g_rs[MM];                         // LN rstd per row
__device__ __align__(16) float g_u1[1024];                       // W @ nw
__device__ __align__(16) float g_u2[1024];                       // W @ nb
__device__ __align__(16) __nv_bfloat16 g_xi [(size_t)MM * DD];   // in_proj xi half bf16
__device__ __align__(16) __nv_bfloat16 g_z  [(size_t)MM * DD];   // in_proj z half bf16
__device__ __align__(16) __nv_bfloat16 g_xcb[(size_t)MM * DD];   // conv+silu bf16
__device__ __align__(16) float g_dbc[(size_t)MM * 48];           // x_proj out compact: [dt_in|B|C]
__device__ __align__(16) __nv_bfloat16 g_ybf[(size_t)MM * DD];   // y bf16
__device__ __align__(16) __nv_bfloat16 g_outTb[(size_t)CC * MM]; // out_proj result, c-major bf16
__device__ __align__(16) __nv_bfloat16 g_wib[1024 * 256];        // (in_proj_w * nw) bf16
__device__ __align__(16) __nv_bfloat16 g_wob[256 * 512];         // out_proj_w bf16
__device__ __align__(16) __nv_bfloat16 g_wxb[64 * 512];          // x_proj_w bf16 padded 48->64
__device__ __align__(16) float g_P [(size_t)NSEQ * NCHUNK * DD * NST];
__device__ __align__(16) float g_he[(size_t)NSEQ * NCHUNK * DD * NST];
__device__ __align__(16) float g_h0[(size_t)NSEQ * NCHUNK * DD * NST];

// ---------------- K0: gather-transpose desc -> g_xg (n,l,c) bf16 ----------------
__global__ void k_trans(const float* __restrict__ d0, const float* __restrict__ d1)
{
    __shared__ float tile[32][33];
    int h  = blockIdx.x;
    int wt = blockIdx.y % 3, ct = blockIdx.y / 3;
    int bd = blockIdx.z;
    int b = bd >> 1, d = bd & 1;
    int w0 = wt * 32, c0 = ct * 32;
    int tx = threadIdx.x, ty = threadIdx.y;

    const float* src = d ? d1 : d0;
    #pragma unroll
    for (int s = 0; s < 4; s++) {
        int cl = ty + s * 8;
        tile[cl][tx] = src[((size_t)(b*CC + c0 + cl)*HH + h)*WW + w0 + tx];
    }
    __syncthreads();

    #pragma unroll
    for (int s = 0; s < 4; s++) {
        int wl = ty + s * 8;
        int w  = w0 + wl;
        float v = tile[tx][wl];
        int k, l;
        if ((h & 1) == 0) {
            if ((w & 1) == 0) { k = 0; l = (h>>1)*96 + (w>>1) + 48*d; }
            else              { k = 2; l = (LL-1) - ((h>>1)*96 + (w>>1) + 48*d); }
        } else {
            if ((w & 1) == 1) { k = 1; l = (w>>1)*96 + (h>>1) + 48*d; }
            else              { k = 3; l = (LL-1) - ((w>>1)*96 + (h>>1) + 48*d); }
        }
        int n = b*4 + k;
        g_xg[((size_t)n*LL + l)*CC + c0 + tx] = __float2bfloat16(v);
    }
}

// ---------------- K0b: per-row LN stats (mean, rstd) ----------------
__global__ void k_stats()
{
    int row = blockIdx.x * 8 + (threadIdx.x >> 5);
    int lane = threadIdx.x & 31;
    const __nv_bfloat16* p = &g_xg[(size_t)row * CC];

    uint4 u = *(const uint4*)&p[lane * 8];
    const __nv_bfloat162* h2 = (const __nv_bfloat162*)&u;
    float s1 = 0.f, s2 = 0.f;
    #pragma unroll
    for (int q = 0; q < 4; q++) {
        float2 f = __bfloat1622float2(h2[q]);
        s1 += f.x + f.y;
        s2 += f.x*f.x + f.y*f.y;
    }
    #pragma unroll
    for (int o = 16; o > 0; o >>= 1) {
        s1 += __shfl_xor_sync(0xffffffffu, s1, o);
        s2 += __shfl_xor_sync(0xffffffffu, s2, o);
    }
    if (lane == 0) {
        float mean = s1 * (1.f/256.f);
        float var  = s2 * (1.f/256.f) - mean*mean;
        g_mu[row] = mean;
        g_rs[row] = rsqrtf(var + 1e-5f);
    }
}

// ---------------- weight conversions ----------------
__global__ void k_cvtw(const float* __restrict__ inw, const float* __restrict__ opw,
                       const float* __restrict__ xpw, const float* __restrict__ nw)
{
    int i = blockIdx.x * 256 + threadIdx.x;
    if (i < 1024*256) g_wib[i] = __float2bfloat16(inw[i] * nw[i & 255]);
    if (i < 256*512)  g_wob[i] = __float2bfloat16(opw[i]);
    if (i < 64*512) {
        int r = i >> 9, cidx = i & 511;
        g_wxb[i] = __float2bfloat16(r < 48 ? xpw[r*512 + cidx] : 0.f);
    }
}

// u1[e] = sum_c W[e,c]*nw[c], u2[e] = sum_c W[e,c]*nb[c]
__global__ void k_prep_u(const float* __restrict__ inw,
                         const float* __restrict__ nw, const float* __restrict__ nb)
{
    int e = blockIdx.x;
    int c = threadIdx.x;
    float wv = inw[e*256 + c];
    float s1 = wv * nw[c], s2 = wv * nb[c];
    #pragma unroll
    for (int o = 16; o > 0; o >>= 1) {
        s1 += __shfl_xor_sync(0xffffffffu, s1, o);
        s2 += __shfl_xor_sync(0xffffffffu, s2, o);
    }
    __shared__ float a1[8], a2[8];
    int wid = c >> 5;
    if ((c & 31) == 0) { a1[wid] = s1; a2[wid] = s2; }
    __syncthreads();
    if (c == 0) {
        float t1 = 0.f, t2 = 0.f;
        #pragma unroll
        for (int q = 0; q < 8; q++) { t1 += a1[q]; t2 += a2[q]; }
        g_u1[e] = t1; g_u2[e] = t2;
    }
}

// ---------------- mma helpers ----------------
__device__ __forceinline__ unsigned int smem_u32(const void* p) {
    return (unsigned int)__cvta_generic_to_shared(p);
}
__device__ __forceinline__ void ldsm4(unsigned int* r, unsigned int addr) {
    asm volatile("ldmatrix.sync.aligned.m8n8.x4.shared.b16 {%0,%1,%2,%3}, [%4];"
                 : "=r"(r[0]), "=r"(r[1]), "=r"(r[2]), "=r"(r[3]) : "r"(addr));
}
__device__ __forceinline__ void mma16816(float* c, const unsigned int* a,
                                         unsigned int b0, unsigned int b1) {
    asm volatile("mma.sync.aligned.m16n8k16.row.col.f32.bf16.bf16.f32 "
                 "{%0,%1,%2,%3},{%4,%5,%6,%7},{%8,%9},{%0,%1,%2,%3};"
                 : "+f"(c[0]), "+f"(c[1]), "+f"(c[2]), "+f"(c[3])
                 : "r"(a[0]), "r"(a[1]), "r"(a[2]), "r"(a[3]), "r"(b0), "r"(b1));
}
__device__ __forceinline__ void cpa16(unsigned int d, const void* s) {
    asm volatile("cp.async.cg.shared.global [%0], [%1], 16;" :: "r"(d), "l"(s));
}
__device__ __forceinline__ void cp_commit() { asm volatile("cp.async.commit_group;"); }
template<int N> __device__ __forceinline__ void cp_wait() {
    asm volatile("cp.async.wait_group %0;" :: "n"(N));
}

// ---------------- hgemm 128x128x32, cp.async double-buffered ----------------
// MODE 1: in_proj with LN fold: out = acc*rs[row] - rs*mu*u1[col] + u2[col]; split bf16 xi/z
// MODE 2: out_proj: bf16 transposed output O1[col*MM + row]
template<int MODE>
__global__ __launch_bounds__(256) void hgemm128(
    const __nv_bfloat16* __restrict__ A, const __nv_bfloat16* __restrict__ B,
    __nv_bfloat16* __restrict__ O1, __nv_bfloat16* __restrict__ O2,
    int Kd)
{
    const int LDS = 40;
    __shared__ __nv_bfloat16 As[2][128 * LDS];
    __shared__ __nv_bfloat16 Bs[2][128 * LDS];

    int tid  = threadIdx.x;
    int wid  = tid >> 5, lane = tid & 31;
    int wm   = (wid & 1) * 64;
    int wn   = (wid >> 1) * 32;
    int m0   = blockIdx.y * 128;
    int n0   = blockIdx.x * 128;

    float c[4][4][4];
    #pragma unroll
    for (int i = 0; i < 4; i++)
        #pragma unroll
        for (int j = 0; j < 4; j++)
            #pragma unroll
            for (int q = 0; q < 4; q++) c[i][j][q] = 0.f;

    int ar = tid >> 2;
    int ac = (tid & 3) * 8;
    int NK = Kd >> 5;

    {   // prefetch stage 0
        cpa16(smem_u32(&As[0][ar*LDS + ac]),        &A[(size_t)(m0 + ar)      * Kd + ac]);
        cpa16(smem_u32(&As[0][(ar+64)*LDS + ac]),   &A[(size_t)(m0 + ar + 64) * Kd + ac]);
        cpa16(smem_u32(&Bs[0][ar*LDS + ac]),        &B[(size_t)(n0 + ar)      * Kd + ac]);
        cpa16(smem_u32(&Bs[0][(ar+64)*LDS + ac]),   &B[(size_t)(n0 + ar + 64) * Kd + ac]);
        cp_commit();
    }

    for (int it = 0; it < NK; it++) {
        if (it + 1 < NK) {
            int st = (it + 1) & 1, k0 = (it + 1) * 32;
            cpa16(smem_u32(&As[st][ar*LDS + ac]),      &A[(size_t)(m0 + ar)      * Kd + k0 + ac]);
            cpa16(smem_u32(&As[st][(ar+64)*LDS + ac]), &A[(size_t)(m0 + ar + 64) * Kd + k0 + ac]);
            cpa16(smem_u32(&Bs[st][ar*LDS + ac]),      &B[(size_t)(n0 + ar)      * Kd + k0 + ac]);
            cpa16(smem_u32(&Bs[st][(ar+64)*LDS + ac]), &B[(size_t)(n0 + ar + 64) * Kd + k0 + ac]);
            cp_commit();
            cp_wait<1>();
        } else {
            cp_wait<0>();
        }
        __syncthreads();

        int cur = it & 1;
        #pragma unroll
        for (int ks = 0; ks < 2; ks++) {
            int kk = ks * 16;
            unsigned int a[4][4], b[2][4];
            #pragma unroll
            for (int i = 0; i < 4; i++)
                ldsm4(a[i], smem_u32(&As[cur][(wm + i*16 + (lane & 15)) * LDS + kk + ((lane >> 4) * 8)]));
            #pragma unroll
            for (int j2 = 0; j2 < 2; j2++)
                ldsm4(b[j2], smem_u32(&Bs[cur][(wn + j2*16 + (lane & 15)) * LDS + kk + ((lane >> 4) * 8)]));
            #pragma unroll
            for (int i = 0; i < 4; i++)
                #pragma unroll
                for (int j2 = 0; j2 < 2; j2++) {
                    mma16816(c[i][2*j2+0], a[i], b[j2][0], b[j2][2]);
                    mma16816(c[i][2*j2+1], a[i], b[j2][1], b[j2][3]);
                }
        }
        __syncthreads();
    }

    int g = lane >> 2, t4 = lane & 3;
    #pragma unroll
    for (int i = 0; i < 4; i++) {
        int r0 = m0 + wm + i*16 + g;
        int r1 = r0 + 8;
        float f0 = 0.f, g0 = 0.f, f1 = 0.f, g1 = 0.f;
        if (MODE == 1) {
            f0 = g_rs[r0]; g0 = -f0 * g_mu[r0];
            f1 = g_rs[r1]; g1 = -f1 * g_mu[r1];
        }
        #pragma unroll
        for (int j = 0; j < 4; j++) {
            int col = n0 + wn + j*8 + t4*2;
            if (MODE == 1) {
                float U10 = g_u1[col], U11 = g_u1[col+1];
                float U20 = g_u2[col], U21 = g_u2[col+1];
                float v00 = c[i][j][0]*f0 + g0*U10 + U20;
                float v01 = c[i][j][1]*f0 + g0*U11 + U21;
                float v10 = c[i][j][2]*f1 + g1*U10 + U20;
                float v11 = c[i][j][3]*f1 + g1*U11 + U21;
                __nv_bfloat162 a01 = __floats2bfloat162_rn(v00, v01);
                __nv_bfloat162 a23 = __floats2bfloat162_rn(v10, v11);
                if (col < 512) {
                    *(__nv_bfloat162*)&O1[(size_t)r0 * 512 + col] = a01;
                    *(__nv_bfloat162*)&O1[(size_t)r1 * 512 + col] = a23;
                } else {
                    *(__nv_bfloat162*)&O2[(size_t)r0 * 512 + col - 512] = a01;
                    *(__nv_bfloat162*)&O2[(size_t)r1 * 512 + col - 512] = a23;
                }
            } else {
                O1[(size_t)col * MM + r0]     = __float2bfloat16(c[i][j][0]);
                O1[(size_t)(col+1) * MM + r0] = __float2bfloat16(c[i][j][1]);
                O1[(size_t)col * MM + r1]     = __float2bfloat16(c[i][j][2]);
                O1[(size_t)(col+1) * MM + r1] = __float2bfloat16(c[i][j][3]);
            }
        }
    }
}

// ---------------- x_proj GEMM with fused conv+silu A-build ----------------
__global__ __launch_bounds__(256) void k_xproj(const float* __restrict__ cw, const float* __restrict__ cb)
{
    const int LDS = 40;
    __shared__ __nv_bfloat16 As[128 * LDS];
    __shared__ __nv_bfloat16 Bs[64 * LDS];
    __shared__ float scw[512*4];
    __shared__ float scb[512];

    int tid = threadIdx.x;
    int wid = tid >> 5, lane = tid & 31;
    int wm  = (wid & 3) * 32;
    int wn  = (wid >> 2) * 32;
    int m0  = blockIdx.x * 128;

    for (int i = tid; i < 2048; i += 256) scw[i] = cw[i];
    for (int i = tid; i < 512;  i += 256) scb[i] = cb[i];

    float c[2][4][4];
    #pragma unroll
    for (int i = 0; i < 2; i++)
        #pragma unroll
        for (int j = 0; j < 4; j++)
            #pragma unroll
            for (int q = 0; q < 4; q++) c[i][j][q] = 0.f;

    int R  = tid >> 2;
    int k8 = (tid & 3) * 8;
    int lr1 = (m0 + R) % LL;
    int lr2 = (m0 + R + 64) % LL;
    __syncthreads();

    for (int k0 = 0; k0 < 512; k0 += 32) {
        #pragma unroll
        for (int pass = 0; pass < 2; pass++) {
            int r  = R + pass*64;
            int m  = m0 + r;
            int lr = pass ? lr2 : lr1;
            float acc[8];
            #pragma unroll
            for (int q = 0; q < 8; q++) acc[q] = scb[k0 + k8 + q];
            #pragma unroll
            for (int t = 0; t < 4; t++) {
                if (lr - 3 + t >= 0) {
                    uint4 u = *(const uint4*)&g_xi[(size_t)(m - 3 + t)*512 + k0 + k8];
                    __nv_bfloat162* p = (__nv_bfloat162*)&u;
                    #pragma unroll
                    for (int q2 = 0; q2 < 4; q2++) {
                        float2 f = __bfloat1622float2(p[q2]);
                        acc[2*q2+0] = fmaf(f.x, scw[(k0+k8+2*q2+0)*4 + t], acc[2*q2+0]);
                        acc[2*q2+1] = fmaf(f.y, scw[(k0+k8+2*q2+1)*4 + t], acc[2*q2+1]);
                    }
                }
            }
            uint4 o;
            __nv_bfloat162* q = (__nv_bfloat162*)&o;
            #pragma unroll
            for (int q2 = 0; q2 < 4; q2++) {
                float v0 = acc[2*q2+0], v1 = acc[2*q2+1];
                v0 = v0 / (1.f + __expf(-v0));
                v1 = v1 / (1.f + __expf(-v1));
                q[q2] = __floats2bfloat162_rn(v0, v1);
            }
            *(uint4*)&As[r * LDS + k8] = o;
            *(uint4*)&g_xcb[(size_t)m * 512 + k0 + k8] = o;
        }
        *(uint4*)&Bs[R * LDS + k8] = *(const uint4*)&g_wxb[(size_t)R * 512 + k0 + k8];
        __syncthreads();

        #pragma unroll
        for (int ks = 0; ks < 2; ks++) {
            int kk = ks * 16;
            unsigned int a[2][4], b[2][4];
            #pragma unroll
            for (int i = 0; i < 2; i++)
                ldsm4(a[i], smem_u32(&As[(wm + i*16 + (lane & 15)) * LDS + kk + ((lane >> 4) * 8)]));
            #pragma unroll
            for (int j2 = 0; j2 < 2; j2++)
                ldsm4(b[j2], smem_u32(&Bs[(wn + j2*16 + (lane & 15)) * LDS + kk + ((lane >> 4) * 8)]));
            #pragma unroll
            for (int i = 0; i < 2; i++)
                #pragma unroll
                for (int j2 = 0; j2 < 2; j2++) {
                    mma16816(c[i][2*j2+0], a[i], b[j2][0], b[j2][2]);
                    mma16816(c[i][2*j2+1], a[i], b[j2][1], b[j2][3]);
                }
        }
        __syncthreads();
    }

    int g = lane >> 2, t4 = lane & 3;
    #pragma unroll
    for (int i = 0; i < 2; i++)
        #pragma unroll
        for (int j = 0; j < 4; j++) {
            int row = m0 + wm + i*16 + g;
            int col = wn + j*8 + t4*2;
            if (col < 48) {   // compact stride-48 dbc
                *(float2*)&g_dbc[(size_t)row * 48 + col]       = make_float2(c[i][j][0], c[i][j][1]);
                *(float2*)&g_dbc[(size_t)(row + 8) * 48 + col] = make_float2(c[i][j][2], c[i][j][3]);
            }
        }
}

// ---------------- scan helpers ----------------
__device__ __forceinline__ float inline_dt(const float* __restrict__ dr, const float* dtwr, float dtbv)
{
    float v = dtbv;
    #pragma unroll
    for (int r = 0; r < RNK; r++) v = fmaf(dr[r], dtwr[r], v);
    return (v > 20.f) ? v : log1pf(__expf(v));
}

// ---------------- scan pass 1 ----------------
__global__ void k_scan1(const float* __restrict__ Alog,
                        const float* __restrict__ dtw, const float* __restrict__ dtb)
{
    __shared__ float sdbc[SUB * 48];
    int n  = blockIdx.z;
    int ch = blockIdx.y;
    int e  = blockIdx.x * 128 + threadIdx.x;

    float a[NST];
    #pragma unroll
    for (int s = 0; s < NST; s++) a[s] = -__expf(Alog[e*NST + s]);
    float a0 = a[0];
    bool fast = (a0 < 0.f);
    #pragma unroll
    for (int s = 0; s < NST; s++)
        fast = fast && (fabsf(a[s]/a0 - (float)(s+1)) < 1e-3f);

    float dtwr[RNK];
    #pragma unroll
    for (int r = 0; r < RNK; r++) dtwr[r] = dtw[e*RNK + r];
    float dtbv = dtb[e];

    float h[NST];
    #pragma unroll
    for (int s = 0; s < NST; s++) h[s] = 0.f;
    float sdt = 0.f;
    int l0 = ch * CH;

    for (int sl = 0; sl < CH; sl += SUB) {
        __syncthreads();
        const float* gsrc = &g_dbc[((size_t)n*LL + l0 + sl) * 48];
        for (int idx = threadIdx.x; idx < SUB*48; idx += 128)
            sdbc[idx] = gsrc[idx];
        __syncthreads();

        for (int r = 0; r < SUB; r++) {
            size_t row = (size_t)n*LL + l0 + sl + r;
            const float* dr = &sdbc[r * 48];
            float dv[RNK], bb[NST];
            #pragma unroll
            for (int q = 0; q < 4; q++) {
                float4 t0 = ((const float4*)dr)[q];
                dv[4*q]=t0.x; dv[4*q+1]=t0.y; dv[4*q+2]=t0.z; dv[4*q+3]=t0.w;
                float4 t1 = ((const float4*)dr)[4+q];
                bb[4*q]=t1.x; bb[4*q+1]=t1.y; bb[4*q+2]=t1.z; bb[4*q+3]=t1.w;
            }
            float dtv = inline_dt(dv, dtwr, dtbv);
            float xcv = __bfloat162float(g_xcb[row*DD + e]);
            float w = dtv * xcv;
            sdt += dtv;
            if (fast) {
                float p  = __expf(dtv * a0);
                float pk = p;
                #pragma unroll
                for (int s = 0; s < NST; s++) { h[s] = fmaf(h[s], pk, w * bb[s]); pk *= p; }
            } else {
                #pragma unroll
                for (int s = 0; s < NST; s++) {
                    float dA = __expf(dtv * a[s]);
                    h[s] = fmaf(h[s], dA, w * bb[s]);
                }
            }
        }
    }

    size_t o = (((size_t)n*NCHUNK + ch)*DD + e) * NST;
    #pragma unroll
    for (int q = 0; q < 4; q++) {
        ((float4*)&g_he[o])[q] = make_float4(h[4*q], h[4*q+1], h[4*q+2], h[4*q+3]);
        ((float4*)&g_P[o])[q] = make_float4(__expf(a[4*q]*sdt),   __expf(a[4*q+1]*sdt),
                                            __expf(a[4*q+2]*sdt), __expf(a[4*q+3]*sdt));
    }
}

// ---------------- carry ----------------
__global__ void k_carry()
{
    int idx = blockIdx.x * 256 + threadIdx.x;
    int e = idx & (DD - 1);
    int n = idx >> 9;

    float hc[NST];
    #pragma unroll
    for (int s = 0; s < NST; s++) hc[s] = 0.f;

    for (int ch = 0; ch < NCHUNK; ch++) {
        size_t o = (((size_t)n*NCHUNK + ch)*DD + e) * NST;
        #pragma unroll
        for (int q = 0; q < 4; q++)
            ((float4*)&g_h0[o])[q] = make_float4(hc[4*q], hc[4*q+1], hc[4*q+2], hc[4*q+3]);
        #pragma unroll
        for (int q = 0; q < 4; q++) {
            float4 P = ((const float4*)&g_P[o])[q];
            float4 E = ((const float4*)&g_he[o])[q];
            hc[4*q+0] = fmaf(P.x, hc[4*q+0], E.x);
            hc[4*q+1] = fmaf(P.y, hc[4*q+1], E.y);
            hc[4*q+2] = fmaf(P.z, hc[4*q+2], E.z);
            hc[4*q+3] = fmaf(P.w, hc[4*q+3], E.w);
        }
    }
}

// ---------------- scan pass 2 ----------------
__global__ void k_scan2(const float* __restrict__ Alog, const float* __restrict__ Dp,
                        const float* __restrict__ dtw, const float* __restrict__ dtb)
{
    __shared__ float sdbc[SUB * 48];
    int n  = blockIdx.z;
    int ch = blockIdx.y;
    int e  = blockIdx.x * 128 + threadIdx.x;

    float a[NST];
    #pragma unroll
    for (int s = 0; s < NST; s++) a[s] = -__expf(Alog[e*NST + s]);
    float a0 = a[0];
    bool fast = (a0 < 0.f);
    #pragma unroll
    for (int s = 0; s < NST; s++)
        fast = fast && (fabsf(a[s]/a0 - (float)(s+1)) < 1e-3f);

    float dtwr[RNK];
    #pragma unroll
    for (int r = 0; r < RNK; r++) dtwr[r] = dtw[e*RNK + r];
    float dtbv = dtb[e];
    float De = Dp[e];

    float h[NST];
    size_t o = (((size_t)n*NCHUNK + ch)*DD + e) * NST;
    #pragma unroll
    for (int q = 0; q < 4; q++) {
        float4 t = ((const float4*)&g_h0[o])[q];
        h[4*q] = t.x; h[4*q+1] = t.y; h[4*q+2] = t.z; h[4*q+3] = t.w;
    }

    int l0 = ch * CH;
    for (int sl = 0; sl < CH; sl += SUB) {
        __syncthreads();
        const float* gsrc = &g_dbc[((size_t)n*LL + l0 + sl) * 48];
        for (int idx = threadIdx.x; idx < SUB*48; idx += 128)
            sdbc[idx] = gsrc[idx];
        __syncthreads();

        for (int r = 0; r < SUB; r++) {
            size_t row = (size_t)n*LL + l0 + sl + r;
            const float* dr = &sdbc[r * 48];
            float dv[RNK], bb[NST], cc[NST];
            #pragma unroll
            for (int q = 0; q < 4; q++) {
                float4 t0 = ((const float4*)dr)[q];
                dv[4*q]=t0.x; dv[4*q+1]=t0.y; dv[4*q+2]=t0.z; dv[4*q+3]=t0.w;
                float4 t1 = ((const float4*)dr)[4+q];
                bb[4*q]=t1.x; bb[4*q+1]=t1.y; bb[4*q+2]=t1.z; bb[4*q+3]=t1.w;
                float4 t2 = ((const float4*)dr)[8+q];
                cc[4*q]=t2.x; cc[4*q+1]=t2.y; cc[4*q+2]=t2.z; cc[4*q+3]=t2.w;
            }
            float dtv = inline_dt(dv, dtwr, dtbv);
            float xcv = __bfloat162float(g_xcb[row*DD + e]);
            float zv  = __bfloat162float(g_z[row*DD + e]);
            float w  = dtv * xcv;
            float yv = 0.f;
            if (fast) {
                float p  = __expf(dtv * a0);
                float pk = p;
                #pragma unroll
                for (int s = 0; s < NST; s++) {
                    h[s] = fmaf(h[s], pk, w * bb[s]);
                    yv   = fmaf(h[s], cc[s], yv);
                    pk  *= p;
                }
            } else {
                #pragma unroll
                for (int s = 0; s < NST; s++) {
                    float dA = __expf(dtv * a[s]);
                    h[s] = fmaf(h[s], dA, w * bb[s]);
                    yv   = fmaf(h[s], cc[s], yv);
                }
            }
            yv = (yv + xcv*De) * (zv / (1.f + __expf(-zv)));
            g_ybf[row*DD + e] = __float2bfloat16(yv);
        }
    }
}

// ---------------- merge + residual ----------------
__global__ void k_final(const float* __restrict__ d0, const float* __restrict__ d1,
                        float* __restrict__ out)
{
    int idx = blockIdx.x * 256 + threadIdx.x;
    int w = idx % 96;
    int t = idx / 96;
    int h = t % 96; t /= 96;
    int c = t % 256; t /= 256;
    int b = t & 3;
    int d = t >> 2;

    int k, l;
    if ((h & 1) == 0) {
        if ((w & 1) == 0) { k = 0; l = (h>>1)*96 + (w>>1) + 48*d; }
        else              { k = 2; l = (LL-1) - ((h>>1)*96 + (w>>1) + 48*d); }
    } else {
        if ((w & 1) == 1) { k = 1; l = (w>>1)*96 + (h>>1) + 48*d; }
        else              { k = 3; l = (LL-1) - ((w>>1)*96 + (h>>1) + 48*d); }
    }
    int n = b*4 + k;
    const float* dsc = d ? d1 : d0;
    int local = idx - d * (NB*CC*HW);

    out[idx] = 2.f*dsc[local] + __bfloat162float(g_outTb[(size_t)c * MM + (size_t)n*LL + l]);
}

// ---------------- host launch ----------------
extern "C" void kernel_launch(void* const* d_in, const int* in_sizes, int n_in,
                              void* d_out, int out_size)
{
    const float* desc0 = (const float*)d_in[0];
    const float* desc1 = (const float*)d_in[1];
    const float* nw    = (const float*)d_in[2];
    const float* nbi   = (const float*)d_in[3];
    const float* inw   = (const float*)d_in[4];
    const float* cw    = (const float*)d_in[5];
    const float* cb    = (const float*)d_in[6];
    const float* xpw   = (const float*)d_in[7];
    const float* dtw   = (const float*)d_in[8];
    const float* dtb   = (const float*)d_in[9];
    const float* alog  = (const float*)d_in[10];
    const float* dpar  = (const float*)d_in[11];
    const float* opw   = (const float*)d_in[12];

    __nv_bfloat16 *p_xg, *p_ybf, *p_wib, *p_wob, *p_xi, *p_z, *p_outTb;
    cudaGetSymbolAddress((void**)&p_xg,  g_xg);
    cudaGetSymbolAddress((void**)&p_xi,  g_xi);
    cudaGetSymbolAddress((void**)&p_z,   g_z);
    cudaGetSymbolAddress((void**)&p_ybf, g_ybf);
    cudaGetSymbolAddress((void**)&p_outTb, g_outTb);
    cudaGetSymbolAddress((void**)&p_wib, g_wib);
    cudaGetSymbolAddress((void**)&p_wob, g_wob);

    // 0. gather-transpose + prep
    k_trans<<<dim3(96, 24, 8), dim3(32, 8)>>>(desc0, desc1);
    k_cvtw<<<1024, 256>>>(inw, opw, xpw, nw);
    k_prep_u<<<1024, 256>>>(inw, nw, nbi);
    k_stats<<<MM/8, 256>>>();
    // 1. in_proj GEMM (LN folded): A = raw gathered x
    hgemm128<1><<<dim3(1024/128, MM/128), 256>>>(p_xg, p_wib, p_xi, p_z, 256);
    // 2. conv+silu fused x_proj
    k_xproj<<<dim3(MM/128), 256>>>(cw, cb);
    // 3. chunked scan
    k_scan1<<<dim3(DD/128, NCHUNK, NSEQ), 128>>>(alog, dtw, dtb);
    k_carry<<<NSEQ*DD/256, 256>>>();
    k_scan2<<<dim3(DD/128, NCHUNK, NSEQ), 128>>>(alog, dpar, dtw, dtb);
    // 4. out_proj -> bf16 transposed
    hgemm128<2><<<dim3(256/128, MM/128), 256>>>(p_ybf, p_wob, p_outTb, nullptr, 512);
    // 5. merge + residual
    k_final<<<dim3(out_size/256), 256>>>(desc0, desc1, (float*)d_out);
}